// round 4
// baseline (speedup 1.0000x reference)
#include <cuda_runtime.h>
#include <cuda_bf16.h>
#include <cstdint>
#include <cstddef>

static constexpr int   N     = 4096;
static constexpr int   NB    = 32;            // 128-tiles per side
static constexpr int   SPLIT = 90;            // bf16 iterations before fp32 polish
static constexpr float CINV  = 1.0f / 1.000001f;

// ---------------------------------------------------------------------------
// Device scratch (allocation-free rule: __device__ globals)
// ---------------------------------------------------------------------------
static __device__ float         g_Js[(size_t)N * N];  // 64 MB symmetrized J (fp32)
static __device__ __nv_bfloat16 g_G [(size_t)N * N];  // 32 MB: Js(bf16) during iters, then G
static __device__ __nv_bfloat16 g_H [(size_t)N * N];  // 32 MB: H = G + G^2
static __device__ float         g_m [2][N];
static __device__ float         g_d [N];
static __device__ float         g_w [N];

// ---------------------------------------------------------------------------
// bf16 MMA wrapper (baseline PTX, sm_80+; no tcgen05 — compute_103 safe)
// ---------------------------------------------------------------------------
__device__ __forceinline__ void mma_bf16(float* c, const uint32_t* a, const uint32_t* b) {
    asm volatile(
        "mma.sync.aligned.m16n8k16.row.col.f32.bf16.bf16.f32 "
        "{%0,%1,%2,%3}, {%4,%5,%6,%7}, {%8,%9}, {%0,%1,%2,%3};\n"
        : "+f"(c[0]), "+f"(c[1]), "+f"(c[2]), "+f"(c[3])
        : "r"(a[0]), "r"(a[1]), "r"(a[2]), "r"(a[3]), "r"(b[0]), "r"(b[1]));
}

// ---------------------------------------------------------------------------
// Block reduction of two partial sums (256 threads)
// ---------------------------------------------------------------------------
__device__ __forceinline__ void block_reduce2(float& s1, float& s2) {
#pragma unroll
    for (int o = 16; o; o >>= 1) {
        s1 += __shfl_xor_sync(0xFFFFFFFFu, s1, o);
        s2 += __shfl_xor_sync(0xFFFFFFFFu, s2, o);
    }
    __shared__ float r1[8], r2[8];
    int lane = threadIdx.x & 31, w = threadIdx.x >> 5;
    if (lane == 0) { r1[w] = s1; r2[w] = s2; }
    __syncthreads();
    if (w == 0) {
        s1 = (lane < 8) ? r1[lane] : 0.f;
        s2 = (lane < 8) ? r2[lane] : 0.f;
#pragma unroll
        for (int o = 4; o; o >>= 1) {
            s1 += __shfl_xor_sync(0xFFFFFFFFu, s1, o);
            s2 += __shfl_xor_sync(0xFFFFFFFFu, s2, o);
        }
    }
}

// ---------------------------------------------------------------------------
// k_zero: clear whole output
// ---------------------------------------------------------------------------
__global__ void k_zero(float* out, long long n) {
    long long i = (long long)blockIdx.x * blockDim.x + threadIdx.x;
    long long stride = (long long)gridDim.x * blockDim.x;
    for (; i < n; i += stride) out[i] = 0.0f;
}

// ---------------------------------------------------------------------------
// k_prep: Js = sym(J) with zero diag (fp32) + bf16 copy into g_G
// ---------------------------------------------------------------------------
__global__ void k_prep(const float* __restrict__ J) {
    __shared__ float ta[32][33];
    __shared__ float tb[32][33];
    int bi = blockIdx.y * 32, bj = blockIdx.x * 32;
    int r = threadIdx.y, c = threadIdx.x;
    ta[r][c] = J[(size_t)(bi + r) * N + (bj + c)];
    tb[r][c] = J[(size_t)(bj + r) * N + (bi + c)];
    __syncthreads();
    int i = bi + r, j = bj + c;
    float v = (i == j) ? 0.0f : 0.5f * (ta[r][c] + tb[c][r]);
    size_t idx = (size_t)i * N + j;
    g_Js[idx] = v;
    g_G[idx]  = __float2bfloat16(v);
}

// ---------------------------------------------------------------------------
// m0 = tanh(h)
// ---------------------------------------------------------------------------
__global__ void k_minit(const float* __restrict__ h) {
    int i = blockIdx.x * blockDim.x + threadIdx.x;
    if (i < N) g_m[0][i] = tanhf(h[i]);
}

// ---------------------------------------------------------------------------
// Fused iteration kernels (BLOCK per row, 256 thr): s1 = Js@m, s2 = (Js^2)@(m(1-m))
// ---------------------------------------------------------------------------
__global__ void __launch_bounds__(256) k_iter_bf16(const float* __restrict__ h, int pin) {
    int row = blockIdx.x;
    const float* mi_v = g_m[pin];
    const uint4* Jr = (const uint4*)(g_G + (size_t)row * N);   // 8 bf16 per uint4; 512 total
    const float4* mv = (const float4*)mi_v;
    float s1 = 0.f, s2 = 0.f;
#pragma unroll
    for (int k = 0; k < 2; k++) {
        int q = threadIdx.x + k * 256;
        uint4 v = Jr[q];
        const __nv_bfloat162* b2 = reinterpret_cast<const __nv_bfloat162*>(&v);
        float4 m0 = mv[2 * q], m1 = mv[2 * q + 1];
        float2 a0 = __bfloat1622float2(b2[0]);
        float2 a1 = __bfloat1622float2(b2[1]);
        float2 a2 = __bfloat1622float2(b2[2]);
        float2 a3 = __bfloat1622float2(b2[3]);
        s1 = fmaf(a0.x, m0.x, s1); s1 = fmaf(a0.y, m0.y, s1);
        s1 = fmaf(a1.x, m0.z, s1); s1 = fmaf(a1.y, m0.w, s1);
        s1 = fmaf(a2.x, m1.x, s1); s1 = fmaf(a2.y, m1.y, s1);
        s1 = fmaf(a3.x, m1.z, s1); s1 = fmaf(a3.y, m1.w, s1);
        s2 = fmaf(a0.x * a0.x, m0.x * (1.f - m0.x), s2);
        s2 = fmaf(a0.y * a0.y, m0.y * (1.f - m0.y), s2);
        s2 = fmaf(a1.x * a1.x, m0.z * (1.f - m0.z), s2);
        s2 = fmaf(a1.y * a1.y, m0.w * (1.f - m0.w), s2);
        s2 = fmaf(a2.x * a2.x, m1.x * (1.f - m1.x), s2);
        s2 = fmaf(a2.y * a2.y, m1.y * (1.f - m1.y), s2);
        s2 = fmaf(a3.x * a3.x, m1.z * (1.f - m1.z), s2);
        s2 = fmaf(a3.y * a3.y, m1.w * (1.f - m1.w), s2);
    }
    block_reduce2(s1, s2);
    if (threadIdx.x == 0) {
        float mi = mi_v[row];
        g_m[pin ^ 1][row] = 0.5f * (mi + tanhf(h[row] + s1 - mi * s2));
    }
}

__global__ void __launch_bounds__(256) k_iter_f32(const float* __restrict__ h, int pin) {
    int row = blockIdx.x;
    const float* mi_v = g_m[pin];
    const float4* Jr = (const float4*)(g_Js + (size_t)row * N);  // 1024 float4
    const float4* mv = (const float4*)mi_v;
    float s1 = 0.f, s2 = 0.f;
#pragma unroll
    for (int k = 0; k < 4; k++) {
        int q = threadIdx.x + k * 256;
        float4 a = Jr[q];
        float4 b = mv[q];
        s1 = fmaf(a.x, b.x, s1); s1 = fmaf(a.y, b.y, s1);
        s1 = fmaf(a.z, b.z, s1); s1 = fmaf(a.w, b.w, s1);
        s2 = fmaf(a.x * a.x, b.x * (1.f - b.x), s2);
        s2 = fmaf(a.y * a.y, b.y * (1.f - b.y), s2);
        s2 = fmaf(a.z * a.z, b.z * (1.f - b.z), s2);
        s2 = fmaf(a.w * a.w, b.w * (1.f - b.w), s2);
    }
    block_reduce2(s1, s2);
    if (threadIdx.x == 0) {
        float mi = mi_v[row];
        g_m[pin ^ 1][row] = 0.5f * (mi + tanhf(h[row] + s1 - mi * s2));
    }
}

// ---------------------------------------------------------------------------
// k_vec: finalize m (in g_m[0] after 100 iters), compute d, w, write m to out
// ---------------------------------------------------------------------------
__global__ void k_vec(float* out, int writeM) {
    int i = blockIdx.x * blockDim.x + threadIdx.x;
    if (i < N) {
        float m = g_m[0][i];
        float d = 1.0f - m * m;
        g_d[i] = d;
        g_w[i] = sqrtf(d);
        if (writeM) out[i] = m;
    }
}

// ---------------------------------------------------------------------------
// k_buildG: G_ij = CINV * w_i * Js_ij * w_j (bf16), overwrites g_G
// ---------------------------------------------------------------------------
__global__ void k_buildG() {
    size_t q = (size_t)blockIdx.x * blockDim.x + threadIdx.x;  // float4 index
    size_t nq = (size_t)N * N / 4;
    if (q >= nq) return;
    size_t base = q * 4;
    int i = (int)(base >> 12);
    int j = (int)(base & (N - 1));
    float4 a = *(const float4*)(g_Js + base);
    float s = CINV * g_w[i];
    float2 r0, r1;
    r0.x = s * g_w[j + 0] * a.x;  r0.y = s * g_w[j + 1] * a.y;
    r1.x = s * g_w[j + 2] * a.z;  r1.y = s * g_w[j + 3] * a.w;
    __nv_bfloat162* dst = reinterpret_cast<__nv_bfloat162*>(g_G + base);
    dst[0] = __float22bfloat162_rn(r0);
    dst[1] = __float22bfloat162_rn(r1);
}

// ---------------------------------------------------------------------------
// k_gemm: 128x128 upper-triangle tile (bi<=bj), bf16 mma.sync, K=4096.
//   pass 1: D = G*G^T       -> H = G + D (bf16)
//   pass 2: D = G*H^T (=S)  -> cov epilogue into out (strictly upper)
// Both operand tiles stored [row][k] in smem (k-contiguous), LDT=40 pad.
// ---------------------------------------------------------------------------
static constexpr int KC  = 32;     // k-chunk
static constexpr int LDT = 40;     // smem row stride (bf16 elems)

__global__ void __launch_bounds__(256) k_gemm(int pass, float* out, long long covBase) {
    __shared__ __nv_bfloat16 sA[2][128 * LDT];
    __shared__ __nv_bfloat16 sB[2][128 * LDT];

    // decode linear block id -> upper-triangle tile (bi, bj)
    int rem = blockIdx.x;
    int bi = 0;
    while (rem >= NB - bi) { rem -= NB - bi; bi++; }
    int bj = bi + rem;
    int i0 = bi * 128, j0 = bj * 128;

    const __nv_bfloat16* Aop = g_G;
    const __nv_bfloat16* Bop = (pass == 1) ? g_G : g_H;

    int tid = threadIdx.x, lane = tid & 31, wid = tid >> 5;
    int wr = wid >> 2, wc = wid & 3;          // warp row (0..1), warp col (0..3)
    int gID = lane >> 2, tig = lane & 3;

    float acc[4][4][4];
#pragma unroll
    for (int a = 0; a < 4; a++)
#pragma unroll
        for (int b = 0; b < 4; b++)
#pragma unroll
            for (int c = 0; c < 4; c++) acc[a][b][c] = 0.f;

    // per-thread gmem slots: q = tid + t*256; r = q>>2 (row), g = q&3 (8-elem k group)
    uint4 ra[2], rb[2];
    int r_[2], g_[2];
#pragma unroll
    for (int t = 0; t < 2; t++) { int q = tid + t * 256; r_[t] = q >> 2; g_[t] = q & 3; }

    // prologue: load + store chunk 0
#pragma unroll
    for (int t = 0; t < 2; t++) {
        ra[t] = *(const uint4*)(Aop + (size_t)(i0 + r_[t]) * N + g_[t] * 8);
        rb[t] = *(const uint4*)(Bop + (size_t)(j0 + r_[t]) * N + g_[t] * 8);
    }
#pragma unroll
    for (int t = 0; t < 2; t++) {
        *(uint4*)&sA[0][r_[t] * LDT + g_[t] * 8] = ra[t];
        *(uint4*)&sB[0][r_[t] * LDT + g_[t] * 8] = rb[t];
    }
    __syncthreads();

    const int NCH = N / KC;   // 128
    for (int c = 0; c < NCH; c++) {
        int buf = c & 1;
        if (c + 1 < NCH) {
            int kc = (c + 1) * KC;
#pragma unroll
            for (int t = 0; t < 2; t++) {
                ra[t] = *(const uint4*)(Aop + (size_t)(i0 + r_[t]) * N + kc + g_[t] * 8);
                rb[t] = *(const uint4*)(Bop + (size_t)(j0 + r_[t]) * N + kc + g_[t] * 8);
            }
        }
#pragma unroll
        for (int kk = 0; kk < KC; kk += 16) {
            uint32_t af[4][4], bf[4][2];
#pragma unroll
            for (int mi = 0; mi < 4; mi++) {
                const __nv_bfloat16* base = &sA[buf][(wr * 64 + mi * 16 + gID) * LDT + kk + tig * 2];
                af[mi][0] = *(const uint32_t*)(base);
                af[mi][1] = *(const uint32_t*)(base + 8 * LDT);
                af[mi][2] = *(const uint32_t*)(base + 8);
                af[mi][3] = *(const uint32_t*)(base + 8 * LDT + 8);
            }
#pragma unroll
            for (int ni = 0; ni < 4; ni++) {
                const __nv_bfloat16* base = &sB[buf][(wc * 32 + ni * 8 + gID) * LDT + kk + tig * 2];
                bf[ni][0] = *(const uint32_t*)(base);
                bf[ni][1] = *(const uint32_t*)(base + 8);
            }
#pragma unroll
            for (int mi = 0; mi < 4; mi++)
#pragma unroll
                for (int ni = 0; ni < 4; ni++)
                    mma_bf16(acc[mi][ni], af[mi], bf[ni]);
        }
        __syncthreads();
        if (c + 1 < NCH) {
            int nb = (c + 1) & 1;
#pragma unroll
            for (int t = 0; t < 2; t++) {
                *(uint4*)&sA[nb][r_[t] * LDT + g_[t] * 8] = ra[t];
                *(uint4*)&sB[nb][r_[t] * LDT + g_[t] * 8] = rb[t];
            }
            __syncthreads();
        }
    }

    // epilogue
#pragma unroll
    for (int mi = 0; mi < 4; mi++) {
#pragma unroll
        for (int r8 = 0; r8 < 2; r8++) {
            int row = i0 + wr * 64 + mi * 16 + gID + r8 * 8;
            if (pass == 1) {
                __nv_bfloat16* dst = g_H + (size_t)row * N;
                const __nv_bfloat16* gsrc = g_G + (size_t)row * N;
#pragma unroll
                for (int ni = 0; ni < 4; ni++) {
                    int col = j0 + wc * 32 + ni * 8 + tig * 2;
                    float2 v;
                    v.x = acc[mi][ni][r8 * 2 + 0] + __bfloat162float(gsrc[col]);
                    v.y = acc[mi][ni][r8 * 2 + 1] + __bfloat162float(gsrc[col + 1]);
                    *(__nv_bfloat162*)(dst + col) = __float22bfloat162_rn(v);
                }
            } else {
                const float* jsrc = g_Js + (size_t)row * N;
                float mrow = g_m[0][row];
                float inv_wr = 1.0f / g_w[row];
#pragma unroll
                for (int ni = 0; ni < 4; ni++) {
                    int col = j0 + wc * 32 + ni * 8 + tig * 2;
#pragma unroll
                    for (int e = 0; e < 2; e++) {
                        int gj = col + e;
                        if (gj > row) {
                            float S = acc[mi][ni][r8 * 2 + e];
                            float cov = mrow * g_m[0][gj]
                                      + CINV * (CINV * jsrc[gj] * g_d[gj] + S * g_w[gj] * inv_wr);
                            out[covBase + (size_t)row * N + gj] = cov;
                        }
                    }
                }
            }
        }
    }
}

// ---------------------------------------------------------------------------
// k_mirrorH: H[r][c] = H[c][r] for r > c (coalesced 32x32 smem transpose)
// ---------------------------------------------------------------------------
__global__ void k_mirrorH() {
    int bx = blockIdx.x, by = blockIdx.y;       // source row tile, source col tile
    if (by < bx) return;
    __shared__ __nv_bfloat16 t[32][33];
    int tx = threadIdx.x, ty = threadIdx.y;
    t[ty][tx] = g_H[(size_t)(bx * 32 + ty) * N + (by * 32 + tx)];
    __syncthreads();
    int dr = by * 32 + ty, dc = bx * 32 + tx;
    if (dr > dc) g_H[(size_t)dr * N + dc] = t[tx][ty];
}

// ---------------------------------------------------------------------------
// kernel_launch
// ---------------------------------------------------------------------------
extern "C" void kernel_launch(void* const* d_in, const int* in_sizes, int n_in,
                              void* d_out, int out_size) {
    const float* h = nullptr;
    const float* J = nullptr;
    for (int i = 0; i < n_in; i++) {
        if (in_sizes[i] == N * N)   J = (const float*)d_in[i];
        else if (in_sizes[i] == N)  h = (const float*)d_in[i];
    }
    float* out = (float*)d_out;
    long long covBase = ((long long)out_size >= (long long)N * N + N) ? N : 0;

    k_zero<<<8192, 256>>>(out, (long long)out_size);
    k_prep<<<dim3(N / 32, N / 32), dim3(32, 32)>>>(J);
    k_minit<<<16, 256>>>(h);
    for (int t = 0; t < 100; t++) {
        if (t < SPLIT) k_iter_bf16<<<N, 256>>>(h, t & 1);
        else           k_iter_f32 <<<N, 256>>>(h, t & 1);
    }
    k_vec<<<16, 256>>>(out, covBase > 0 ? 1 : 0);
    k_buildG<<<(int)(((size_t)N * N / 4 + 255) / 256), 256>>>();
    k_gemm<<<NB * (NB + 1) / 2, 256>>>(1, out, covBase);
    k_mirrorH<<<dim3(N / 32, N / 32), dim3(32, 32)>>>();
    k_gemm<<<NB * (NB + 1) / 2, 256>>>(2, out, covBase);
}

// round 5
// speedup vs baseline: 1.6272x; 1.6272x over previous
#include <cuda_runtime.h>
#include <cuda_bf16.h>
#include <cstdint>
#include <cstddef>

static constexpr int   N     = 4096;
static constexpr int   NB    = 32;            // 128-tiles per side
static constexpr int   NT    = 128;           // 32-tiles per side
static constexpr int   TOT_ITERS = 30;        // fixed point converged to <1e-9 by 30
static constexpr int   SPLIT = 20;            // bf16 iterations before fp32 polish
static constexpr float CINV  = 1.0f / 1.000001f;

// ---------------------------------------------------------------------------
// Device scratch (allocation-free rule: __device__ globals)
// ---------------------------------------------------------------------------
static __device__ float         g_Js[(size_t)N * N];  // 64 MB symmetrized J (fp32)
static __device__ __nv_bfloat16 g_G [(size_t)N * N];  // 32 MB: Js(bf16) during iters, then G
static __device__ __nv_bfloat16 g_H [(size_t)N * N];  // 32 MB: H = G + G^2
static __device__ float         g_m [2][N];
static __device__ float         g_d [N];
static __device__ float         g_w [N];

// ---------------------------------------------------------------------------
// bf16 MMA wrapper (baseline PTX, sm_80+; no tcgen05 — compute_103 safe)
// ---------------------------------------------------------------------------
__device__ __forceinline__ void mma_bf16(float* c, const uint32_t* a, const uint32_t* b) {
    asm volatile(
        "mma.sync.aligned.m16n8k16.row.col.f32.bf16.bf16.f32 "
        "{%0,%1,%2,%3}, {%4,%5,%6,%7}, {%8,%9}, {%0,%1,%2,%3};\n"
        : "+f"(c[0]), "+f"(c[1]), "+f"(c[2]), "+f"(c[3])
        : "r"(a[0]), "r"(a[1]), "r"(a[2]), "r"(a[3]), "r"(b[0]), "r"(b[1]));
}

// ---------------------------------------------------------------------------
// k_zero: clear whole output
// ---------------------------------------------------------------------------
__global__ void k_zero(float* out, long long n) {
    long long i = (long long)blockIdx.x * blockDim.x + threadIdx.x;
    long long stride = (long long)gridDim.x * blockDim.x;
    for (; i < n; i += stride) out[i] = 0.0f;
}

// ---------------------------------------------------------------------------
// k_prep: Js = sym(J) with zero diag (fp32) + bf16 copy; tile-pair version
// (reads each J tile once; grid = upper-triangle 32x32 tiles)
// ---------------------------------------------------------------------------
__global__ void k_prep(const float* __restrict__ J) {
    int rem = blockIdx.x;
    int bi = 0;
    while (rem >= NT - bi) { rem -= NT - bi; bi++; }
    int bj = bi + rem;
    __shared__ float ta[32][33];
    __shared__ float tb[32][33];
    int r = threadIdx.y, c = threadIdx.x;
    ta[r][c] = J[(size_t)(bi * 32 + r) * N + (bj * 32 + c)];
    tb[r][c] = J[(size_t)(bj * 32 + r) * N + (bi * 32 + c)];
    __syncthreads();
    {
        int gi = bi * 32 + r, gj = bj * 32 + c;
        float v = (gi == gj) ? 0.0f : 0.5f * (ta[r][c] + tb[c][r]);
        size_t idx = (size_t)gi * N + gj;
        g_Js[idx] = v;
        g_G[idx]  = __float2bfloat16(v);
    }
    if (bi != bj) {
        int gi = bj * 32 + r, gj = bi * 32 + c;
        float v = 0.5f * (tb[r][c] + ta[c][r]);
        size_t idx = (size_t)gi * N + gj;
        g_Js[idx] = v;
        g_G[idx]  = __float2bfloat16(v);
    }
}

// ---------------------------------------------------------------------------
// m0 = tanh(h)
// ---------------------------------------------------------------------------
__global__ void k_minit(const float* __restrict__ h) {
    int i = blockIdx.x * blockDim.x + threadIdx.x;
    if (i < N) g_m[0][i] = tanhf(h[i]);
}

// ---------------------------------------------------------------------------
// Fused iteration kernels: 8 ROWS per block (m loaded once serves 8 rows,
// 8 independent row streams -> MLP 8). s1 = Js@m, s2 = (Js^2)@(m(1-m)).
// ---------------------------------------------------------------------------
static constexpr int RPB = 8;

__global__ void __launch_bounds__(256) k_iter_bf16(const float* __restrict__ h, int pin) {
    int row0 = blockIdx.x * RPB;
    const float* mi_v = g_m[pin];
    const float4* mv = (const float4*)mi_v;
    float s1[RPB], s2[RPB];
#pragma unroll
    for (int r = 0; r < RPB; r++) { s1[r] = 0.f; s2[r] = 0.f; }

#pragma unroll
    for (int k = 0; k < 2; k++) {
        int q = threadIdx.x + k * 256;         // uint4 index (8 bf16), 512 per row
        float4 ma = mv[2 * q], mb = mv[2 * q + 1];
        float pa[8] = {ma.x, ma.y, ma.z, ma.w, mb.x, mb.y, mb.z, mb.w};
        float pb[8];
#pragma unroll
        for (int e = 0; e < 8; e++) pb[e] = pa[e] * (1.f - pa[e]);
#pragma unroll
        for (int r = 0; r < RPB; r++) {
            uint4 v = *(const uint4*)(g_G + (size_t)(row0 + r) * N + q * 8);
            const __nv_bfloat162* b2 = reinterpret_cast<const __nv_bfloat162*>(&v);
            float2 a0 = __bfloat1622float2(b2[0]);
            float2 a1 = __bfloat1622float2(b2[1]);
            float2 a2 = __bfloat1622float2(b2[2]);
            float2 a3 = __bfloat1622float2(b2[3]);
            float av[8] = {a0.x, a0.y, a1.x, a1.y, a2.x, a2.y, a3.x, a3.y};
#pragma unroll
            for (int e = 0; e < 8; e++) {
                s1[r] = fmaf(av[e], pa[e], s1[r]);
                s2[r] = fmaf(av[e] * av[e], pb[e], s2[r]);
            }
        }
    }

    __shared__ float rs1[8][RPB], rs2[8][RPB];
    int lane = threadIdx.x & 31, w = threadIdx.x >> 5;
#pragma unroll
    for (int r = 0; r < RPB; r++) {
#pragma unroll
        for (int o = 16; o; o >>= 1) {
            s1[r] += __shfl_xor_sync(0xFFFFFFFFu, s1[r], o);
            s2[r] += __shfl_xor_sync(0xFFFFFFFFu, s2[r], o);
        }
        if (lane == 0) { rs1[w][r] = s1[r]; rs2[w][r] = s2[r]; }
    }
    __syncthreads();
    if (threadIdx.x < RPB) {
        int r = threadIdx.x;
        float a = 0.f, b = 0.f;
#pragma unroll
        for (int ww = 0; ww < 8; ww++) { a += rs1[ww][r]; b += rs2[ww][r]; }
        int row = row0 + r;
        float mi = mi_v[row];
        g_m[pin ^ 1][row] = 0.5f * (mi + tanhf(h[row] + a - mi * b));
    }
}

__global__ void __launch_bounds__(256) k_iter_f32(const float* __restrict__ h, int pin) {
    int row0 = blockIdx.x * RPB;
    const float* mi_v = g_m[pin];
    const float4* mv = (const float4*)mi_v;
    float s1[RPB], s2[RPB];
#pragma unroll
    for (int r = 0; r < RPB; r++) { s1[r] = 0.f; s2[r] = 0.f; }

#pragma unroll
    for (int k = 0; k < 4; k++) {
        int q = threadIdx.x + k * 256;         // float4 index, 1024 per row
        float4 mq = mv[q];
        float pa[4] = {mq.x, mq.y, mq.z, mq.w};
        float pb[4];
#pragma unroll
        for (int e = 0; e < 4; e++) pb[e] = pa[e] * (1.f - pa[e]);
#pragma unroll
        for (int r = 0; r < RPB; r++) {
            float4 a = *(const float4*)(g_Js + (size_t)(row0 + r) * N + q * 4);
            float av[4] = {a.x, a.y, a.z, a.w};
#pragma unroll
            for (int e = 0; e < 4; e++) {
                s1[r] = fmaf(av[e], pa[e], s1[r]);
                s2[r] = fmaf(av[e] * av[e], pb[e], s2[r]);
            }
        }
    }

    __shared__ float rs1[8][RPB], rs2[8][RPB];
    int lane = threadIdx.x & 31, w = threadIdx.x >> 5;
#pragma unroll
    for (int r = 0; r < RPB; r++) {
#pragma unroll
        for (int o = 16; o; o >>= 1) {
            s1[r] += __shfl_xor_sync(0xFFFFFFFFu, s1[r], o);
            s2[r] += __shfl_xor_sync(0xFFFFFFFFu, s2[r], o);
        }
        if (lane == 0) { rs1[w][r] = s1[r]; rs2[w][r] = s2[r]; }
    }
    __syncthreads();
    if (threadIdx.x < RPB) {
        int r = threadIdx.x;
        float a = 0.f, b = 0.f;
#pragma unroll
        for (int ww = 0; ww < 8; ww++) { a += rs1[ww][r]; b += rs2[ww][r]; }
        int row = row0 + r;
        float mi = mi_v[row];
        g_m[pin ^ 1][row] = 0.5f * (mi + tanhf(h[row] + a - mi * b));
    }
}

// ---------------------------------------------------------------------------
// k_vec: finalize m (in g_m[0] after TOT_ITERS), compute d, w, write m to out
// ---------------------------------------------------------------------------
__global__ void k_vec(float* out, int writeM) {
    int i = blockIdx.x * blockDim.x + threadIdx.x;
    if (i < N) {
        float m = g_m[0][i];
        float d = 1.0f - m * m;
        g_d[i] = d;
        g_w[i] = sqrtf(d);
        if (writeM) out[i] = m;
    }
}

// ---------------------------------------------------------------------------
// k_buildG: G_ij = CINV * w_i * Js_ij * w_j (bf16), overwrites g_G
// ---------------------------------------------------------------------------
__global__ void k_buildG() {
    size_t q = (size_t)blockIdx.x * blockDim.x + threadIdx.x;  // float4 index
    size_t nq = (size_t)N * N / 4;
    if (q >= nq) return;
    size_t base = q * 4;
    int i = (int)(base >> 12);
    int j = (int)(base & (N - 1));
    float4 a = *(const float4*)(g_Js + base);
    float s = CINV * g_w[i];
    float2 r0, r1;
    r0.x = s * g_w[j + 0] * a.x;  r0.y = s * g_w[j + 1] * a.y;
    r1.x = s * g_w[j + 2] * a.z;  r1.y = s * g_w[j + 3] * a.w;
    __nv_bfloat162* dst = reinterpret_cast<__nv_bfloat162*>(g_G + base);
    dst[0] = __float22bfloat162_rn(r0);
    dst[1] = __float22bfloat162_rn(r1);
}

// ---------------------------------------------------------------------------
// k_gemm: 128x128 upper-triangle tile (bi<=bj), bf16 mma.sync, K=4096.
//   pass 1: D = G*G^T       -> H = G + D (bf16)
//   pass 2: D = G*H^T (=S)  -> cov epilogue into out (strictly upper)
// Both operand tiles stored [row][k] in smem (k-contiguous), LDT=40 pad.
// ---------------------------------------------------------------------------
static constexpr int KC  = 32;     // k-chunk
static constexpr int LDT = 40;     // smem row stride (bf16 elems)

__global__ void __launch_bounds__(256) k_gemm(int pass, float* out, long long covBase) {
    __shared__ __nv_bfloat16 sA[2][128 * LDT];
    __shared__ __nv_bfloat16 sB[2][128 * LDT];

    int rem = blockIdx.x;
    int bi = 0;
    while (rem >= NB - bi) { rem -= NB - bi; bi++; }
    int bj = bi + rem;
    int i0 = bi * 128, j0 = bj * 128;

    const __nv_bfloat16* Aop = g_G;
    const __nv_bfloat16* Bop = (pass == 1) ? g_G : g_H;

    int tid = threadIdx.x, lane = tid & 31, wid = tid >> 5;
    int wr = wid >> 2, wc = wid & 3;
    int gID = lane >> 2, tig = lane & 3;

    float acc[4][4][4];
#pragma unroll
    for (int a = 0; a < 4; a++)
#pragma unroll
        for (int b = 0; b < 4; b++)
#pragma unroll
            for (int c = 0; c < 4; c++) acc[a][b][c] = 0.f;

    uint4 ra[2], rb[2];
    int r_[2], g_[2];
#pragma unroll
    for (int t = 0; t < 2; t++) { int q = tid + t * 256; r_[t] = q >> 2; g_[t] = q & 3; }

#pragma unroll
    for (int t = 0; t < 2; t++) {
        ra[t] = *(const uint4*)(Aop + (size_t)(i0 + r_[t]) * N + g_[t] * 8);
        rb[t] = *(const uint4*)(Bop + (size_t)(j0 + r_[t]) * N + g_[t] * 8);
    }
#pragma unroll
    for (int t = 0; t < 2; t++) {
        *(uint4*)&sA[0][r_[t] * LDT + g_[t] * 8] = ra[t];
        *(uint4*)&sB[0][r_[t] * LDT + g_[t] * 8] = rb[t];
    }
    __syncthreads();

    const int NCH = N / KC;   // 128
    for (int c = 0; c < NCH; c++) {
        int buf = c & 1;
        if (c + 1 < NCH) {
            int kc = (c + 1) * KC;
#pragma unroll
            for (int t = 0; t < 2; t++) {
                ra[t] = *(const uint4*)(Aop + (size_t)(i0 + r_[t]) * N + kc + g_[t] * 8);
                rb[t] = *(const uint4*)(Bop + (size_t)(j0 + r_[t]) * N + kc + g_[t] * 8);
            }
        }
#pragma unroll
        for (int kk = 0; kk < KC; kk += 16) {
            uint32_t af[4][4], bf[4][2];
#pragma unroll
            for (int mi = 0; mi < 4; mi++) {
                const __nv_bfloat16* base = &sA[buf][(wr * 64 + mi * 16 + gID) * LDT + kk + tig * 2];
                af[mi][0] = *(const uint32_t*)(base);
                af[mi][1] = *(const uint32_t*)(base + 8 * LDT);
                af[mi][2] = *(const uint32_t*)(base + 8);
                af[mi][3] = *(const uint32_t*)(base + 8 * LDT + 8);
            }
#pragma unroll
            for (int ni = 0; ni < 4; ni++) {
                const __nv_bfloat16* base = &sB[buf][(wc * 32 + ni * 8 + gID) * LDT + kk + tig * 2];
                bf[ni][0] = *(const uint32_t*)(base);
                bf[ni][1] = *(const uint32_t*)(base + 8);
            }
#pragma unroll
            for (int mi = 0; mi < 4; mi++)
#pragma unroll
                for (int ni = 0; ni < 4; ni++)
                    mma_bf16(acc[mi][ni], af[mi], bf[ni]);
        }
        __syncthreads();
        if (c + 1 < NCH) {
            int nb = (c + 1) & 1;
#pragma unroll
            for (int t = 0; t < 2; t++) {
                *(uint4*)&sA[nb][r_[t] * LDT + g_[t] * 8] = ra[t];
                *(uint4*)&sB[nb][r_[t] * LDT + g_[t] * 8] = rb[t];
            }
            __syncthreads();
        }
    }

#pragma unroll
    for (int mi = 0; mi < 4; mi++) {
#pragma unroll
        for (int r8 = 0; r8 < 2; r8++) {
            int row = i0 + wr * 64 + mi * 16 + gID + r8 * 8;
            if (pass == 1) {
                __nv_bfloat16* dst = g_H + (size_t)row * N;
                const __nv_bfloat16* gsrc = g_G + (size_t)row * N;
#pragma unroll
                for (int ni = 0; ni < 4; ni++) {
                    int col = j0 + wc * 32 + ni * 8 + tig * 2;
                    float2 v;
                    v.x = acc[mi][ni][r8 * 2 + 0] + __bfloat162float(gsrc[col]);
                    v.y = acc[mi][ni][r8 * 2 + 1] + __bfloat162float(gsrc[col + 1]);
                    *(__nv_bfloat162*)(dst + col) = __float22bfloat162_rn(v);
                }
            } else {
                const float* jsrc = g_Js + (size_t)row * N;
                float mrow = g_m[0][row];
                float inv_wr = 1.0f / g_w[row];
#pragma unroll
                for (int ni = 0; ni < 4; ni++) {
                    int col = j0 + wc * 32 + ni * 8 + tig * 2;
#pragma unroll
                    for (int e = 0; e < 2; e++) {
                        int gj = col + e;
                        if (gj > row) {
                            float S = acc[mi][ni][r8 * 2 + e];
                            float cov = mrow * g_m[0][gj]
                                      + CINV * (CINV * jsrc[gj] * g_d[gj] + S * g_w[gj] * inv_wr);
                            out[covBase + (size_t)row * N + gj] = cov;
                        }
                    }
                }
            }
        }
    }
}

// ---------------------------------------------------------------------------
// k_mirrorH: H[r][c] = H[c][r] for r > c (coalesced 32x32 smem transpose)
// ---------------------------------------------------------------------------
__global__ void k_mirrorH() {
    int bx = blockIdx.x, by = blockIdx.y;
    if (by < bx) return;
    __shared__ __nv_bfloat16 t[32][33];
    int tx = threadIdx.x, ty = threadIdx.y;
    t[ty][tx] = g_H[(size_t)(bx * 32 + ty) * N + (by * 32 + tx)];
    __syncthreads();
    int dr = by * 32 + ty, dc = bx * 32 + tx;
    if (dr > dc) g_H[(size_t)dr * N + dc] = t[tx][ty];
}

// ---------------------------------------------------------------------------
// kernel_launch
// ---------------------------------------------------------------------------
extern "C" void kernel_launch(void* const* d_in, const int* in_sizes, int n_in,
                              void* d_out, int out_size) {
    const float* h = nullptr;
    const float* J = nullptr;
    for (int i = 0; i < n_in; i++) {
        if (in_sizes[i] == N * N)   J = (const float*)d_in[i];
        else if (in_sizes[i] == N)  h = (const float*)d_in[i];
    }
    float* out = (float*)d_out;
    long long covBase = ((long long)out_size >= (long long)N * N + N) ? N : 0;

    k_zero<<<8192, 256>>>(out, (long long)out_size);
    k_prep<<<NT * (NT + 1) / 2, dim3(32, 32)>>>(J);
    k_minit<<<16, 256>>>(h);
    for (int t = 0; t < TOT_ITERS; t++) {
        if (t < SPLIT) k_iter_bf16<<<N / RPB, 256>>>(h, t & 1);
        else           k_iter_f32 <<<N / RPB, 256>>>(h, t & 1);
    }
    k_vec<<<16, 256>>>(out, covBase > 0 ? 1 : 0);
    k_buildG<<<(int)(((size_t)N * N / 4 + 255) / 256), 256>>>();
    k_gemm<<<NB * (NB + 1) / 2, 256>>>(1, out, covBase);
    k_mirrorH<<<dim3(N / 32, N / 32), dim3(32, 32)>>>();
    k_gemm<<<NB * (NB + 1) / 2, 256>>>(2, out, covBase);
}

// round 6
// speedup vs baseline: 1.7931x; 1.1020x over previous
#include <cuda_runtime.h>
#include <cuda_bf16.h>
#include <cstdint>
#include <cstddef>

static constexpr int   N     = 4096;
static constexpr int   NB    = 32;            // 128-tiles per side
static constexpr int   NT    = 128;           // 32-tiles per side
static constexpr int   TOT_ITERS = 30;        // fixed point converged to <1e-9 by 30
static constexpr int   SPLIT = 24;            // bf16 iterations before fp32 polish
static constexpr float CINV  = 1.0f / 1.000001f;

// ---------------------------------------------------------------------------
// Device scratch (allocation-free rule: __device__ globals)
// ---------------------------------------------------------------------------
static __device__ float         g_Js[(size_t)N * N];  // 64 MB symmetrized J (fp32)
static __device__ __nv_bfloat16 g_G [(size_t)N * N];  // 32 MB: Js(bf16) during iters, then G
static __device__ __nv_bfloat16 g_H [(size_t)N * N];  // 32 MB: H = G + G^2
static __device__ float         g_m [2][N];
static __device__ float         g_d [N];
static __device__ float         g_w [N];

// ---------------------------------------------------------------------------
// bf16 MMA wrapper (baseline PTX, sm_80+; no tcgen05 — compute_103 safe)
// ---------------------------------------------------------------------------
__device__ __forceinline__ void mma_bf16(float* c, const uint32_t* a, const uint32_t* b) {
    asm volatile(
        "mma.sync.aligned.m16n8k16.row.col.f32.bf16.bf16.f32 "
        "{%0,%1,%2,%3}, {%4,%5,%6,%7}, {%8,%9}, {%0,%1,%2,%3};\n"
        : "+f"(c[0]), "+f"(c[1]), "+f"(c[2]), "+f"(c[3])
        : "r"(a[0]), "r"(a[1]), "r"(a[2]), "r"(a[3]), "r"(b[0]), "r"(b[1]));
}

__device__ __forceinline__ uint32_t smem_u32(const void* p) {
    uint32_t a;
    asm("{ .reg .u64 t; cvta.to.shared.u64 t, %1; cvt.u32.u64 %0, t; }" : "=r"(a) : "l"(p));
    return a;
}
__device__ __forceinline__ void cp16(uint32_t dst, const void* src) {
    asm volatile("cp.async.cg.shared.global [%0], [%1], 16;" :: "r"(dst), "l"(src));
}
#define CP_COMMIT()  asm volatile("cp.async.commit_group;" ::: "memory")
#define CP_WAIT0()   asm volatile("cp.async.wait_group 0;" ::: "memory")

// ---------------------------------------------------------------------------
// k_zero: clear whole output (vectorized)
// ---------------------------------------------------------------------------
__global__ void k_zero(float* out, long long n) {
    long long nq = n >> 2;
    float4* o4 = (float4*)out;
    long long i = (long long)blockIdx.x * blockDim.x + threadIdx.x;
    long long stride = (long long)gridDim.x * blockDim.x;
    for (; i < nq; i += stride) o4[i] = make_float4(0.f, 0.f, 0.f, 0.f);
    if (i == nq)  // first thread past the end handles the tail
        for (long long t = nq << 2; t < n; t++) out[t] = 0.f;
}

// ---------------------------------------------------------------------------
// k_prep: Js = sym(J) with zero diag (fp32) + bf16 copy; tile-pair version
// ---------------------------------------------------------------------------
__global__ void k_prep(const float* __restrict__ J) {
    int rem = blockIdx.x;
    int bi = 0;
    while (rem >= NT - bi) { rem -= NT - bi; bi++; }
    int bj = bi + rem;
    __shared__ float ta[32][33];
    __shared__ float tb[32][33];
    int r = threadIdx.y, c = threadIdx.x;
    ta[r][c] = J[(size_t)(bi * 32 + r) * N + (bj * 32 + c)];
    tb[r][c] = J[(size_t)(bj * 32 + r) * N + (bi * 32 + c)];
    __syncthreads();
    {
        int gi = bi * 32 + r, gj = bj * 32 + c;
        float v = (gi == gj) ? 0.0f : 0.5f * (ta[r][c] + tb[c][r]);
        size_t idx = (size_t)gi * N + gj;
        g_Js[idx] = v;
        g_G[idx]  = __float2bfloat16(v);
    }
    if (bi != bj) {
        int gi = bj * 32 + r, gj = bi * 32 + c;
        float v = 0.5f * (tb[r][c] + ta[c][r]);
        size_t idx = (size_t)gi * N + gj;
        g_Js[idx] = v;
        g_G[idx]  = __float2bfloat16(v);
    }
}

// ---------------------------------------------------------------------------
// m0 = tanh(h)
// ---------------------------------------------------------------------------
__global__ void k_minit(const float* __restrict__ h) {
    int i = blockIdx.x * blockDim.x + threadIdx.x;
    if (i < N) g_m[0][i] = tanhf(h[i]);
}

// ---------------------------------------------------------------------------
// Iteration finish: block-reduce R row sums + damped tanh update
// ---------------------------------------------------------------------------
template <int R>
__device__ __forceinline__ void iter_finish(float (&s1)[R], float (&s2)[R],
                                            const float* __restrict__ h,
                                            const float* mi_v, float* mo_v, int row0) {
    __shared__ float rs1[8][R], rs2[8][R];
    int lane = threadIdx.x & 31, w = threadIdx.x >> 5;
#pragma unroll
    for (int r = 0; r < R; r++) {
#pragma unroll
        for (int o = 16; o; o >>= 1) {
            s1[r] += __shfl_xor_sync(0xFFFFFFFFu, s1[r], o);
            s2[r] += __shfl_xor_sync(0xFFFFFFFFu, s2[r], o);
        }
        if (lane == 0) { rs1[w][r] = s1[r]; rs2[w][r] = s2[r]; }
    }
    __syncthreads();
    if (threadIdx.x < R) {
        int r = threadIdx.x;
        float a = 0.f, b = 0.f;
#pragma unroll
        for (int ww = 0; ww < 8; ww++) { a += rs1[ww][r]; b += rs2[ww][r]; }
        int row = row0 + r;
        float mi = mi_v[row];
        mo_v[row] = 0.5f * (mi + tanhf(h[row] + a - mi * b));
    }
}

// ---------------------------------------------------------------------------
// bf16 iteration: 4 rows/block, grid=1024. s1=Js@m, s2=(Js^2)@(m(1-m))
// ---------------------------------------------------------------------------
__global__ void __launch_bounds__(256) k_iter_bf16(const float* __restrict__ h, int pin) {
    int row0 = blockIdx.x * 4;
    const float* mi_v = g_m[pin];
    const float4* mv = (const float4*)mi_v;
    float s1[4] = {0.f, 0.f, 0.f, 0.f}, s2[4] = {0.f, 0.f, 0.f, 0.f};

#pragma unroll
    for (int k = 0; k < 2; k++) {
        int q = threadIdx.x + k * 256;      // uint4 index (8 bf16); 512 per row
        uint4 v[4];
#pragma unroll
        for (int r = 0; r < 4; r++)
            v[r] = *(const uint4*)(g_G + (size_t)(row0 + r) * N + (size_t)q * 8);
        float4 ma = mv[2 * q], mb = mv[2 * q + 1];
        float pa[8] = {ma.x, ma.y, ma.z, ma.w, mb.x, mb.y, mb.z, mb.w};
        float pb[8];
#pragma unroll
        for (int e = 0; e < 8; e++) pb[e] = pa[e] * (1.f - pa[e]);
#pragma unroll
        for (int r = 0; r < 4; r++) {
            const __nv_bfloat162* b2 = reinterpret_cast<const __nv_bfloat162*>(&v[r]);
            float2 a0 = __bfloat1622float2(b2[0]);
            float2 a1 = __bfloat1622float2(b2[1]);
            float2 a2 = __bfloat1622float2(b2[2]);
            float2 a3 = __bfloat1622float2(b2[3]);
            float av[8] = {a0.x, a0.y, a1.x, a1.y, a2.x, a2.y, a3.x, a3.y};
#pragma unroll
            for (int e = 0; e < 8; e++) {
                s1[r] = fmaf(av[e], pa[e], s1[r]);
                s2[r] = fmaf(av[e] * av[e], pb[e], s2[r]);
            }
        }
    }
    iter_finish<4>(s1, s2, h, mi_v, g_m[pin ^ 1], row0);
}

// ---------------------------------------------------------------------------
// fp32 polish iteration: 2 rows/block, grid=2048
// ---------------------------------------------------------------------------
__global__ void __launch_bounds__(256) k_iter_f32(const float* __restrict__ h, int pin) {
    int row0 = blockIdx.x * 2;
    const float* mi_v = g_m[pin];
    const float4* mv = (const float4*)mi_v;
    float s1[2] = {0.f, 0.f}, s2[2] = {0.f, 0.f};

#pragma unroll
    for (int k = 0; k < 4; k++) {
        int q = threadIdx.x + k * 256;      // float4 index; 1024 per row
        float4 a0 = *(const float4*)(g_Js + (size_t)row0 * N + (size_t)q * 4);
        float4 a1 = *(const float4*)(g_Js + (size_t)(row0 + 1) * N + (size_t)q * 4);
        float4 mq = mv[q];
        float pa[4] = {mq.x, mq.y, mq.z, mq.w};
        float pb[4];
#pragma unroll
        for (int e = 0; e < 4; e++) pb[e] = pa[e] * (1.f - pa[e]);
        float av0[4] = {a0.x, a0.y, a0.z, a0.w};
        float av1[4] = {a1.x, a1.y, a1.z, a1.w};
#pragma unroll
        for (int e = 0; e < 4; e++) {
            s1[0] = fmaf(av0[e], pa[e], s1[0]);
            s2[0] = fmaf(av0[e] * av0[e], pb[e], s2[0]);
            s1[1] = fmaf(av1[e], pa[e], s1[1]);
            s2[1] = fmaf(av1[e] * av1[e], pb[e], s2[1]);
        }
    }
    iter_finish<2>(s1, s2, h, mi_v, g_m[pin ^ 1], row0);
}

// ---------------------------------------------------------------------------
// k_vec: finalize m, compute d, w, write m to out
// ---------------------------------------------------------------------------
__global__ void k_vec(float* out, int writeM) {
    int i = blockIdx.x * blockDim.x + threadIdx.x;
    if (i < N) {
        float m = g_m[0][i];
        float d = 1.0f - m * m;
        g_d[i] = d;
        g_w[i] = sqrtf(d);
        if (writeM) out[i] = m;
    }
}

// ---------------------------------------------------------------------------
// k_buildG: G_ij = CINV * w_i * G_ij * w_j (in-place over bf16(Js))
// ---------------------------------------------------------------------------
__global__ void k_buildG() {
    size_t q = (size_t)blockIdx.x * blockDim.x + threadIdx.x;  // 8-elem group
    size_t nq = (size_t)N * N / 8;
    if (q >= nq) return;
    size_t base = q * 8;
    int i = (int)(base >> 12);
    int j = (int)(base & (N - 1));
    uint4 v = *(const uint4*)(g_G + base);
    const __nv_bfloat162* b2 = reinterpret_cast<const __nv_bfloat162*>(&v);
    float s = CINV * g_w[i];
    uint4 outv;
    __nv_bfloat162* o2 = reinterpret_cast<__nv_bfloat162*>(&outv);
#pragma unroll
    for (int e = 0; e < 4; e++) {
        float2 a = __bfloat1622float2(b2[e]);
        float2 r;
        r.x = s * g_w[j + 2 * e]     * a.x;
        r.y = s * g_w[j + 2 * e + 1] * a.y;
        o2[e] = __float22bfloat162_rn(r);
    }
    *(uint4*)(g_G + base) = outv;
}

// ---------------------------------------------------------------------------
// k_gemm: 128x128 upper-triangle tile (bi<=bj), bf16 mma.sync, K=4096.
//   pass 1: D = G*G^T       -> H = G + D (bf16)
//   pass 2: D = G*H^T (=S)  -> cov epilogue into out (strictly upper)
// cp.async double-buffered, 1 sync per chunk.
// ---------------------------------------------------------------------------
static constexpr int KC  = 32;     // k-chunk
static constexpr int LDT = 40;     // smem row stride (bf16 elems)

__global__ void __launch_bounds__(256) k_gemm(int pass, float* out, long long covBase) {
    __shared__ __align__(16) __nv_bfloat16 sA[2][128 * LDT];
    __shared__ __align__(16) __nv_bfloat16 sB[2][128 * LDT];

    int rem = blockIdx.x;
    int bi = 0;
    while (rem >= NB - bi) { rem -= NB - bi; bi++; }
    int bj = bi + rem;
    int i0 = bi * 128, j0 = bj * 128;

    const __nv_bfloat16* Aop = g_G;
    const __nv_bfloat16* Bop = (pass == 1) ? g_G : g_H;

    int tid = threadIdx.x, lane = tid & 31, wid = tid >> 5;
    int wr = wid >> 2, wc = wid & 3;
    int gID = lane >> 2, tig = lane & 3;

    uint32_t sAu = smem_u32(&sA[0][0]);
    uint32_t sBu = smem_u32(&sB[0][0]);
    const uint32_t BUFB = 128 * LDT * 2;   // bytes per buffer

    float acc[4][4][4];
#pragma unroll
    for (int a = 0; a < 4; a++)
#pragma unroll
        for (int b = 0; b < 4; b++)
#pragma unroll
            for (int c = 0; c < 4; c++) acc[a][b][c] = 0.f;

    // per-thread copy slots: q = tid + t*256; r = q>>2 (row), g = q&3 (8-elem group)
    int r_[2], g_[2];
    uint32_t soff[2];
#pragma unroll
    for (int t = 0; t < 2; t++) {
        int q = tid + t * 256;
        r_[t] = q >> 2; g_[t] = q & 3;
        soff[t] = (uint32_t)(r_[t] * LDT + g_[t] * 8) * 2;
    }

    // prologue: async-load chunk 0 into buffer 0
#pragma unroll
    for (int t = 0; t < 2; t++) {
        cp16(sAu + soff[t], Aop + (size_t)(i0 + r_[t]) * N + g_[t] * 8);
        cp16(sBu + soff[t], Bop + (size_t)(j0 + r_[t]) * N + g_[t] * 8);
    }
    CP_COMMIT();
    CP_WAIT0();
    __syncthreads();

    const int NCH = N / KC;   // 128
    for (int c = 0; c < NCH; c++) {
        int buf = c & 1;
        if (c + 1 < NCH) {
            int kc = (c + 1) * KC;
            uint32_t bo = (uint32_t)((c + 1) & 1) * BUFB;
#pragma unroll
            for (int t = 0; t < 2; t++) {
                cp16(sAu + bo + soff[t], Aop + (size_t)(i0 + r_[t]) * N + kc + g_[t] * 8);
                cp16(sBu + bo + soff[t], Bop + (size_t)(j0 + r_[t]) * N + kc + g_[t] * 8);
            }
            CP_COMMIT();
        }
#pragma unroll
        for (int kk = 0; kk < KC; kk += 16) {
            uint32_t af[4][4], bf[4][2];
#pragma unroll
            for (int mi = 0; mi < 4; mi++) {
                const __nv_bfloat16* base = &sA[buf][(wr * 64 + mi * 16 + gID) * LDT + kk + tig * 2];
                af[mi][0] = *(const uint32_t*)(base);
                af[mi][1] = *(const uint32_t*)(base + 8 * LDT);
                af[mi][2] = *(const uint32_t*)(base + 8);
                af[mi][3] = *(const uint32_t*)(base + 8 * LDT + 8);
            }
#pragma unroll
            for (int ni = 0; ni < 4; ni++) {
                const __nv_bfloat16* base = &sB[buf][(wc * 32 + ni * 8 + gID) * LDT + kk + tig * 2];
                bf[ni][0] = *(const uint32_t*)(base);
                bf[ni][1] = *(const uint32_t*)(base + 8);
            }
#pragma unroll
            for (int mi = 0; mi < 4; mi++)
#pragma unroll
                for (int ni = 0; ni < 4; ni++)
                    mma_bf16(acc[mi][ni], af[mi], bf[ni]);
        }
        if (c + 1 < NCH) CP_WAIT0();
        __syncthreads();
    }

    // epilogue
#pragma unroll
    for (int mi = 0; mi < 4; mi++) {
#pragma unroll
        for (int r8 = 0; r8 < 2; r8++) {
            int row = i0 + wr * 64 + mi * 16 + gID + r8 * 8;
            if (pass == 1) {
                __nv_bfloat16* dst = g_H + (size_t)row * N;
                const __nv_bfloat16* gsrc = g_G + (size_t)row * N;
#pragma unroll
                for (int ni = 0; ni < 4; ni++) {
                    int col = j0 + wc * 32 + ni * 8 + tig * 2;
                    float2 v;
                    v.x = acc[mi][ni][r8 * 2 + 0] + __bfloat162float(gsrc[col]);
                    v.y = acc[mi][ni][r8 * 2 + 1] + __bfloat162float(gsrc[col + 1]);
                    *(__nv_bfloat162*)(dst + col) = __float22bfloat162_rn(v);
                }
            } else {
                const float* jsrc = g_Js + (size_t)row * N;
                float mrow = g_m[0][row];
                float inv_wr = 1.0f / g_w[row];
#pragma unroll
                for (int ni = 0; ni < 4; ni++) {
                    int col = j0 + wc * 32 + ni * 8 + tig * 2;
#pragma unroll
                    for (int e = 0; e < 2; e++) {
                        int gj = col + e;
                        if (gj > row) {
                            float S = acc[mi][ni][r8 * 2 + e];
                            float cov = mrow * g_m[0][gj]
                                      + CINV * (CINV * jsrc[gj] * g_d[gj] + S * g_w[gj] * inv_wr);
                            out[covBase + (size_t)row * N + gj] = cov;
                        }
                    }
                }
            }
        }
    }
}

// ---------------------------------------------------------------------------
// k_mirrorH: H[r][c] = H[c][r] for r > c
// ---------------------------------------------------------------------------
__global__ void k_mirrorH() {
    int bx = blockIdx.x, by = blockIdx.y;
    if (by < bx) return;
    __shared__ __nv_bfloat16 t[32][33];
    int tx = threadIdx.x, ty = threadIdx.y;
    t[ty][tx] = g_H[(size_t)(bx * 32 + ty) * N + (by * 32 + tx)];
    __syncthreads();
    int dr = by * 32 + ty, dc = bx * 32 + tx;
    if (dr > dc) g_H[(size_t)dr * N + dc] = t[tx][ty];
}

// ---------------------------------------------------------------------------
// kernel_launch
// ---------------------------------------------------------------------------
extern "C" void kernel_launch(void* const* d_in, const int* in_sizes, int n_in,
                              void* d_out, int out_size) {
    const float* h = nullptr;
    const float* J = nullptr;
    for (int i = 0; i < n_in; i++) {
        if (in_sizes[i] == N * N)   J = (const float*)d_in[i];
        else if (in_sizes[i] == N)  h = (const float*)d_in[i];
    }
    float* out = (float*)d_out;
    long long covBase = ((long long)out_size >= (long long)N * N + N) ? N : 0;

    k_zero<<<4096, 256>>>(out, (long long)out_size);
    k_prep<<<NT * (NT + 1) / 2, dim3(32, 32)>>>(J);
    k_minit<<<16, 256>>>(h);
    for (int t = 0; t < TOT_ITERS; t++) {
        if (t < SPLIT) k_iter_bf16<<<N / 4, 256>>>(h, t & 1);
        else           k_iter_f32 <<<N / 2, 256>>>(h, t & 1);
    }
    k_vec<<<16, 256>>>(out, covBase > 0 ? 1 : 0);
    k_buildG<<<(int)(((size_t)N * N / 8 + 255) / 256), 256>>>();
    k_gemm<<<NB * (NB + 1) / 2, 256>>>(1, out, covBase);
    k_mirrorH<<<dim3(N / 32, N / 32), dim3(32, 32)>>>();
    k_gemm<<<NB * (NB + 1) / 2, 256>>>(2, out, covBase);
}

// round 7
// speedup vs baseline: 1.8141x; 1.0117x over previous
#include <cuda_runtime.h>
#include <cuda_bf16.h>
#include <cstdint>
#include <cstddef>

static constexpr int   N     = 4096;
static constexpr int   NB    = 32;            // 128-tiles per side
static constexpr int   NT    = 128;           // 32-tiles per side
static constexpr int   TOT_ITERS = 24;        // 18 bf16 + 6 fp32 polish (even -> m ends in g_m[0])
static constexpr int   SPLIT = 18;
static constexpr float CINV  = 1.0f / 1.000001f;

// ---------------------------------------------------------------------------
// Device scratch (allocation-free rule: __device__ globals)
// ---------------------------------------------------------------------------
static __device__ float         g_Js[(size_t)N * N];  // 64 MB symmetrized J (fp32)
static __device__ __nv_bfloat16 g_G [(size_t)N * N];  // 32 MB: Js(bf16) during iters, then G
static __device__ __nv_bfloat16 g_H [(size_t)N * N];  // 32 MB: H = G + G^2
static __device__ float         g_m [2][N];
static __device__ float         g_d [N];
static __device__ float         g_w [N];

// ---------------------------------------------------------------------------
// bf16 MMA wrapper (baseline PTX, sm_80+; no tcgen05 — compute_103 safe)
// ---------------------------------------------------------------------------
__device__ __forceinline__ void mma_bf16(float* c, const uint32_t* a, const uint32_t* b) {
    asm volatile(
        "mma.sync.aligned.m16n8k16.row.col.f32.bf16.bf16.f32 "
        "{%0,%1,%2,%3}, {%4,%5,%6,%7}, {%8,%9}, {%0,%1,%2,%3};\n"
        : "+f"(c[0]), "+f"(c[1]), "+f"(c[2]), "+f"(c[3])
        : "r"(a[0]), "r"(a[1]), "r"(a[2]), "r"(a[3]), "r"(b[0]), "r"(b[1]));
}

__device__ __forceinline__ uint32_t smem_u32(const void* p) {
    uint32_t a;
    asm("{ .reg .u64 t; cvta.to.shared.u64 t, %1; cvt.u32.u64 %0, t; }" : "=r"(a) : "l"(p));
    return a;
}
__device__ __forceinline__ void cp16(uint32_t dst, const void* src) {
    asm volatile("cp.async.cg.shared.global [%0], [%1], 16;" :: "r"(dst), "l"(src));
}
#define CP_COMMIT()  asm volatile("cp.async.commit_group;" ::: "memory")
#define CP_WAIT0()   asm volatile("cp.async.wait_group 0;" ::: "memory")

// ---------------------------------------------------------------------------
// k_zero: clear whole output (vectorized)
// ---------------------------------------------------------------------------
__global__ void k_zero(float* out, long long n) {
    long long nq = n >> 2;
    float4* o4 = (float4*)out;
    long long i = (long long)blockIdx.x * blockDim.x + threadIdx.x;
    long long stride = (long long)gridDim.x * blockDim.x;
    for (; i < nq; i += stride) o4[i] = make_float4(0.f, 0.f, 0.f, 0.f);
    if (i == nq)
        for (long long t = nq << 2; t < n; t++) out[t] = 0.f;
}

// ---------------------------------------------------------------------------
// k_prep: Js = sym(J) with zero diag (fp32) + bf16 copy; tile-pair version
// ---------------------------------------------------------------------------
__global__ void k_prep(const float* __restrict__ J) {
    int rem = blockIdx.x;
    int bi = 0;
    while (rem >= NT - bi) { rem -= NT - bi; bi++; }
    int bj = bi + rem;
    __shared__ float ta[32][33];
    __shared__ float tb[32][33];
    int r = threadIdx.y, c = threadIdx.x;
    ta[r][c] = J[(size_t)(bi * 32 + r) * N + (bj * 32 + c)];
    tb[r][c] = J[(size_t)(bj * 32 + r) * N + (bi * 32 + c)];
    __syncthreads();
    {
        int gi = bi * 32 + r, gj = bj * 32 + c;
        float v = (gi == gj) ? 0.0f : 0.5f * (ta[r][c] + tb[c][r]);
        size_t idx = (size_t)gi * N + gj;
        g_Js[idx] = v;
        g_G[idx]  = __float2bfloat16(v);
    }
    if (bi != bj) {
        int gi = bj * 32 + r, gj = bi * 32 + c;
        float v = 0.5f * (tb[r][c] + ta[c][r]);
        size_t idx = (size_t)gi * N + gj;
        g_Js[idx] = v;
        g_G[idx]  = __float2bfloat16(v);
    }
}

// ---------------------------------------------------------------------------
// m0 = tanh(h)
// ---------------------------------------------------------------------------
__global__ void k_minit(const float* __restrict__ h) {
    int i = blockIdx.x * blockDim.x + threadIdx.x;
    if (i < N) g_m[0][i] = tanhf(h[i]);
}

// ---------------------------------------------------------------------------
// Iteration finish: block-reduce R row sums + damped tanh update
// ---------------------------------------------------------------------------
template <int R>
__device__ __forceinline__ void iter_finish(float (&s1)[R], float (&s2)[R],
                                            const float* __restrict__ h,
                                            const float* mi_v, float* mo_v, int row0) {
    __shared__ float rs1[8][R], rs2[8][R];
    int lane = threadIdx.x & 31, w = threadIdx.x >> 5;
#pragma unroll
    for (int r = 0; r < R; r++) {
#pragma unroll
        for (int o = 16; o; o >>= 1) {
            s1[r] += __shfl_xor_sync(0xFFFFFFFFu, s1[r], o);
            s2[r] += __shfl_xor_sync(0xFFFFFFFFu, s2[r], o);
        }
        if (lane == 0) { rs1[w][r] = s1[r]; rs2[w][r] = s2[r]; }
    }
    __syncthreads();
    if (threadIdx.x < R) {
        int r = threadIdx.x;
        float a = 0.f, b = 0.f;
#pragma unroll
        for (int ww = 0; ww < 8; ww++) { a += rs1[ww][r]; b += rs2[ww][r]; }
        int row = row0 + r;
        float mi = mi_v[row];
        mo_v[row] = 0.5f * (mi + tanhf(h[row] + a - mi * b));
    }
}

// ---------------------------------------------------------------------------
// bf16 iteration: 4 rows/block via cp.async smem slab (32 KB in flight/CTA).
// s1 = Js@m, s2 = (Js*Js)@(m(1-m))
// ---------------------------------------------------------------------------
__global__ void __launch_bounds__(256) k_iter_bf16(const float* __restrict__ h, int pin) {
    __shared__ __align__(16) __nv_bfloat16 sj[4][N];   // 32 KB
    int row0 = blockIdx.x * 4;
    const float* mi_v = g_m[pin];
    const float4* mv = (const float4*)mi_v;
    uint32_t sb = smem_u32(&sj[0][0]);

    // stage all 4 rows: 2048 x 16B slots; slot q -> row q>>9, chunk q&511
#pragma unroll
    for (int t = 0; t < 8; t++) {
        int q = threadIdx.x + t * 256;
        int r = q >> 9, c = q & 511;
        cp16(sb + (uint32_t)q * 16, g_G + (size_t)(row0 + r) * N + (size_t)c * 8);
    }
    CP_COMMIT();
    CP_WAIT0();
    __syncthreads();

    float s1[4] = {0.f, 0.f, 0.f, 0.f}, s2[4] = {0.f, 0.f, 0.f, 0.f};
#pragma unroll
    for (int k = 0; k < 2; k++) {
        int q = threadIdx.x + k * 256;      // 16B chunk within each row
        float4 ma = mv[2 * q], mb = mv[2 * q + 1];
        float pa[8] = {ma.x, ma.y, ma.z, ma.w, mb.x, mb.y, mb.z, mb.w};
        float pb[8];
#pragma unroll
        for (int e = 0; e < 8; e++) pb[e] = pa[e] * (1.f - pa[e]);
#pragma unroll
        for (int r = 0; r < 4; r++) {
            uint4 v = *(const uint4*)&sj[r][q * 8];
            const __nv_bfloat162* b2 = reinterpret_cast<const __nv_bfloat162*>(&v);
            float2 a0 = __bfloat1622float2(b2[0]);
            float2 a1 = __bfloat1622float2(b2[1]);
            float2 a2 = __bfloat1622float2(b2[2]);
            float2 a3 = __bfloat1622float2(b2[3]);
            float av[8] = {a0.x, a0.y, a1.x, a1.y, a2.x, a2.y, a3.x, a3.y};
#pragma unroll
            for (int e = 0; e < 8; e++) {
                s1[r] = fmaf(av[e], pa[e], s1[r]);
                s2[r] = fmaf(av[e] * av[e], pb[e], s2[r]);
            }
        }
    }
    iter_finish<4>(s1, s2, h, mi_v, g_m[pin ^ 1], row0);
}

// ---------------------------------------------------------------------------
// fp32 polish iteration: 2 rows/block via cp.async smem slab (32 KB/CTA)
// ---------------------------------------------------------------------------
__global__ void __launch_bounds__(256) k_iter_f32(const float* __restrict__ h, int pin) {
    __shared__ __align__(16) float sj[2][N];           // 32 KB
    int row0 = blockIdx.x * 2;
    const float* mi_v = g_m[pin];
    const float4* mv = (const float4*)mi_v;
    uint32_t sb = smem_u32(&sj[0][0]);

    // stage 2 rows: 2048 x 16B slots; slot q -> row q>>10, chunk q&1023
#pragma unroll
    for (int t = 0; t < 8; t++) {
        int q = threadIdx.x + t * 256;
        int r = q >> 10, c = q & 1023;
        cp16(sb + (uint32_t)q * 16, g_Js + (size_t)(row0 + r) * N + (size_t)c * 4);
    }
    CP_COMMIT();
    CP_WAIT0();
    __syncthreads();

    const float4* s0 = (const float4*)&sj[0][0];
    const float4* s1v = (const float4*)&sj[1][0];
    float s1[2] = {0.f, 0.f}, s2[2] = {0.f, 0.f};
#pragma unroll
    for (int k = 0; k < 4; k++) {
        int q = threadIdx.x + k * 256;      // float4 index within each row
        float4 a0 = s0[q];
        float4 a1 = s1v[q];
        float4 mq = mv[q];
        float pa[4] = {mq.x, mq.y, mq.z, mq.w};
        float pb[4];
#pragma unroll
        for (int e = 0; e < 4; e++) pb[e] = pa[e] * (1.f - pa[e]);
        float av0[4] = {a0.x, a0.y, a0.z, a0.w};
        float av1[4] = {a1.x, a1.y, a1.z, a1.w};
#pragma unroll
        for (int e = 0; e < 4; e++) {
            s1[0] = fmaf(av0[e], pa[e], s1[0]);
            s2[0] = fmaf(av0[e] * av0[e], pb[e], s2[0]);
            s1[1] = fmaf(av1[e], pa[e], s1[1]);
            s2[1] = fmaf(av1[e] * av1[e], pb[e], s2[1]);
        }
    }
    iter_finish<2>(s1, s2, h, mi_v, g_m[pin ^ 1], row0);
}

// ---------------------------------------------------------------------------
// k_vec: finalize m, compute d, w, write m to out
// ---------------------------------------------------------------------------
__global__ void k_vec(float* out, int writeM) {
    int i = blockIdx.x * blockDim.x + threadIdx.x;
    if (i < N) {
        float m = g_m[0][i];
        float d = 1.0f - m * m;
        g_d[i] = d;
        g_w[i] = sqrtf(d);
        if (writeM) out[i] = m;
    }
}

// ---------------------------------------------------------------------------
// k_buildG: G_ij = CINV * w_i * G_ij * w_j (in-place over bf16(Js))
// ---------------------------------------------------------------------------
__global__ void k_buildG() {
    size_t q = (size_t)blockIdx.x * blockDim.x + threadIdx.x;  // 8-elem group
    size_t nq = (size_t)N * N / 8;
    if (q >= nq) return;
    size_t base = q * 8;
    int i = (int)(base >> 12);
    int j = (int)(base & (N - 1));
    uint4 v = *(const uint4*)(g_G + base);
    const __nv_bfloat162* b2 = reinterpret_cast<const __nv_bfloat162*>(&v);
    float s = CINV * g_w[i];
    uint4 outv;
    __nv_bfloat162* o2 = reinterpret_cast<__nv_bfloat162*>(&outv);
#pragma unroll
    for (int e = 0; e < 4; e++) {
        float2 a = __bfloat1622float2(b2[e]);
        float2 r;
        r.x = s * g_w[j + 2 * e]     * a.x;
        r.y = s * g_w[j + 2 * e + 1] * a.y;
        o2[e] = __float22bfloat162_rn(r);
    }
    *(uint4*)(g_G + base) = outv;
}

// ---------------------------------------------------------------------------
// k_gemm: 128x128 upper-triangle tile (bi<=bj), bf16 mma.sync, K=4096.
//   pass 1: D = G*G^T       -> H = G + D (bf16)
//   pass 2: D = G*H^T (=S)  -> cov epilogue into out (strictly upper)
// cp.async double-buffered, 1 sync per chunk.
// ---------------------------------------------------------------------------
static constexpr int KC  = 32;     // k-chunk
static constexpr int LDT = 40;     // smem row stride (bf16 elems)

__global__ void __launch_bounds__(256) k_gemm(int pass, float* out, long long covBase) {
    __shared__ __align__(16) __nv_bfloat16 sA[2][128 * LDT];
    __shared__ __align__(16) __nv_bfloat16 sB[2][128 * LDT];

    int rem = blockIdx.x;
    int bi = 0;
    while (rem >= NB - bi) { rem -= NB - bi; bi++; }
    int bj = bi + rem;
    int i0 = bi * 128, j0 = bj * 128;

    const __nv_bfloat16* Aop = g_G;
    const __nv_bfloat16* Bop = (pass == 1) ? g_G : g_H;

    int tid = threadIdx.x, lane = tid & 31, wid = tid >> 5;
    int wr = wid >> 2, wc = wid & 3;
    int gID = lane >> 2, tig = lane & 3;

    uint32_t sAu = smem_u32(&sA[0][0]);
    uint32_t sBu = smem_u32(&sB[0][0]);
    const uint32_t BUFB = 128 * LDT * 2;   // bytes per buffer

    float acc[4][4][4];
#pragma unroll
    for (int a = 0; a < 4; a++)
#pragma unroll
        for (int b = 0; b < 4; b++)
#pragma unroll
            for (int c = 0; c < 4; c++) acc[a][b][c] = 0.f;

    int r_[2], g_[2];
    uint32_t soff[2];
#pragma unroll
    for (int t = 0; t < 2; t++) {
        int q = tid + t * 256;
        r_[t] = q >> 2; g_[t] = q & 3;
        soff[t] = (uint32_t)(r_[t] * LDT + g_[t] * 8) * 2;
    }

#pragma unroll
    for (int t = 0; t < 2; t++) {
        cp16(sAu + soff[t], Aop + (size_t)(i0 + r_[t]) * N + g_[t] * 8);
        cp16(sBu + soff[t], Bop + (size_t)(j0 + r_[t]) * N + g_[t] * 8);
    }
    CP_COMMIT();
    CP_WAIT0();
    __syncthreads();

    const int NCH = N / KC;   // 128
    for (int c = 0; c < NCH; c++) {
        int buf = c & 1;
        if (c + 1 < NCH) {
            int kc = (c + 1) * KC;
            uint32_t bo = (uint32_t)((c + 1) & 1) * BUFB;
#pragma unroll
            for (int t = 0; t < 2; t++) {
                cp16(sAu + bo + soff[t], Aop + (size_t)(i0 + r_[t]) * N + kc + g_[t] * 8);
                cp16(sBu + bo + soff[t], Bop + (size_t)(j0 + r_[t]) * N + kc + g_[t] * 8);
            }
            CP_COMMIT();
        }
#pragma unroll
        for (int kk = 0; kk < KC; kk += 16) {
            uint32_t af[4][4], bf[4][2];
#pragma unroll
            for (int mi = 0; mi < 4; mi++) {
                const __nv_bfloat16* base = &sA[buf][(wr * 64 + mi * 16 + gID) * LDT + kk + tig * 2];
                af[mi][0] = *(const uint32_t*)(base);
                af[mi][1] = *(const uint32_t*)(base + 8 * LDT);
                af[mi][2] = *(const uint32_t*)(base + 8);
                af[mi][3] = *(const uint32_t*)(base + 8 * LDT + 8);
            }
#pragma unroll
            for (int ni = 0; ni < 4; ni++) {
                const __nv_bfloat16* base = &sB[buf][(wc * 32 + ni * 8 + gID) * LDT + kk + tig * 2];
                bf[ni][0] = *(const uint32_t*)(base);
                bf[ni][1] = *(const uint32_t*)(base + 8);
            }
#pragma unroll
            for (int mi = 0; mi < 4; mi++)
#pragma unroll
                for (int ni = 0; ni < 4; ni++)
                    mma_bf16(acc[mi][ni], af[mi], bf[ni]);
        }
        if (c + 1 < NCH) CP_WAIT0();
        __syncthreads();
    }

    // epilogue
#pragma unroll
    for (int mi = 0; mi < 4; mi++) {
#pragma unroll
        for (int r8 = 0; r8 < 2; r8++) {
            int row = i0 + wr * 64 + mi * 16 + gID + r8 * 8;
            if (pass == 1) {
                __nv_bfloat16* dst = g_H + (size_t)row * N;
                const __nv_bfloat16* gsrc = g_G + (size_t)row * N;
#pragma unroll
                for (int ni = 0; ni < 4; ni++) {
                    int col = j0 + wc * 32 + ni * 8 + tig * 2;
                    float2 v;
                    v.x = acc[mi][ni][r8 * 2 + 0] + __bfloat162float(gsrc[col]);
                    v.y = acc[mi][ni][r8 * 2 + 1] + __bfloat162float(gsrc[col + 1]);
                    *(__nv_bfloat162*)(dst + col) = __float22bfloat162_rn(v);
                }
            } else {
                const float* jsrc = g_Js + (size_t)row * N;
                float mrow = g_m[0][row];
                float inv_wr = 1.0f / g_w[row];
#pragma unroll
                for (int ni = 0; ni < 4; ni++) {
                    int col = j0 + wc * 32 + ni * 8 + tig * 2;
#pragma unroll
                    for (int e = 0; e < 2; e++) {
                        int gj = col + e;
                        if (gj > row) {
                            float S = acc[mi][ni][r8 * 2 + e];
                            float cov = mrow * g_m[0][gj]
                                      + CINV * (CINV * jsrc[gj] * g_d[gj] + S * g_w[gj] * inv_wr);
                            out[covBase + (size_t)row * N + gj] = cov;
                        }
                    }
                }
            }
        }
    }
}

// ---------------------------------------------------------------------------
// k_mirrorH: H[r][c] = H[c][r] for r > c
// ---------------------------------------------------------------------------
__global__ void k_mirrorH() {
    int bx = blockIdx.x, by = blockIdx.y;
    if (by < bx) return;
    __shared__ __nv_bfloat16 t[32][33];
    int tx = threadIdx.x, ty = threadIdx.y;
    t[ty][tx] = g_H[(size_t)(bx * 32 + ty) * N + (by * 32 + tx)];
    __syncthreads();
    int dr = by * 32 + ty, dc = bx * 32 + tx;
    if (dr > dc) g_H[(size_t)dr * N + dc] = t[tx][ty];
}

// ---------------------------------------------------------------------------
// kernel_launch
// ---------------------------------------------------------------------------
extern "C" void kernel_launch(void* const* d_in, const int* in_sizes, int n_in,
                              void* d_out, int out_size) {
    const float* h = nullptr;
    const float* J = nullptr;
    for (int i = 0; i < n_in; i++) {
        if (in_sizes[i] == N * N)   J = (const float*)d_in[i];
        else if (in_sizes[i] == N)  h = (const float*)d_in[i];
    }
    float* out = (float*)d_out;
    long long covBase = ((long long)out_size >= (long long)N * N + N) ? N : 0;

    k_zero<<<4096, 256>>>(out, (long long)out_size);
    k_prep<<<NT * (NT + 1) / 2, dim3(32, 32)>>>(J);
    k_minit<<<16, 256>>>(h);
    for (int t = 0; t < TOT_ITERS; t++) {
        if (t < SPLIT) k_iter_bf16<<<N / 4, 256>>>(h, t & 1);
        else           k_iter_f32 <<<N / 2, 256>>>(h, t & 1);
    }
    k_vec<<<16, 256>>>(out, covBase > 0 ? 1 : 0);
    k_buildG<<<(int)(((size_t)N * N / 8 + 255) / 256), 256>>>();
    k_gemm<<<NB * (NB + 1) / 2, 256>>>(1, out, covBase);
    k_mirrorH<<<dim3(N / 32, N / 32), dim3(32, 32)>>>();
    k_gemm<<<NB * (NB + 1) / 2, 256>>>(2, out, covBase);
}

// round 8
// speedup vs baseline: 1.9974x; 1.1010x over previous
#include <cuda_runtime.h>
#include <cuda_bf16.h>
#include <cstdint>
#include <cstddef>

static constexpr int   N     = 4096;
static constexpr int   NB    = 32;            // 128-tiles per side
static constexpr int   NT    = 128;           // 32-tiles per side
static constexpr int   TOT_ITERS = 24;        // 18 bf16 + 6 fp32 polish (even -> m ends in g_m[0])
static constexpr int   SPLIT = 18;
static constexpr float CINV  = 1.0f / 1.000001f;

// ---------------------------------------------------------------------------
// Device scratch (allocation-free rule: __device__ globals)
// ---------------------------------------------------------------------------
static __device__ float         g_Js[(size_t)N * N];  // 64 MB symmetrized J (fp32)
static __device__ __nv_bfloat16 g_G [(size_t)N * N];  // 32 MB: Js(bf16) during iters, then G
static __device__ __nv_bfloat16 g_H [(size_t)N * N];  // 32 MB: H = G + G^2
static __device__ float         g_m [2][N];
static __device__ float         g_d [N];
static __device__ float         g_w [N];

// ---------------------------------------------------------------------------
// PTX wrappers (all baseline PTX: sm_75/sm_80 features, compute_103-safe)
// ---------------------------------------------------------------------------
__device__ __forceinline__ void mma_bf16(float* c, const uint32_t* a, const uint32_t* b) {
    asm volatile(
        "mma.sync.aligned.m16n8k16.row.col.f32.bf16.bf16.f32 "
        "{%0,%1,%2,%3}, {%4,%5,%6,%7}, {%8,%9}, {%0,%1,%2,%3};\n"
        : "+f"(c[0]), "+f"(c[1]), "+f"(c[2]), "+f"(c[3])
        : "r"(a[0]), "r"(a[1]), "r"(a[2]), "r"(a[3]), "r"(b[0]), "r"(b[1]));
}
__device__ __forceinline__ void ldmatrix_x4(uint32_t* r, uint32_t addr) {
    asm volatile("ldmatrix.sync.aligned.m8n8.x4.shared.b16 {%0,%1,%2,%3}, [%4];"
                 : "=r"(r[0]), "=r"(r[1]), "=r"(r[2]), "=r"(r[3]) : "r"(addr));
}
__device__ __forceinline__ void ldmatrix_x2(uint32_t* r, uint32_t addr) {
    asm volatile("ldmatrix.sync.aligned.m8n8.x2.shared.b16 {%0,%1}, [%2];"
                 : "=r"(r[0]), "=r"(r[1]) : "r"(addr));
}
__device__ __forceinline__ uint32_t smem_u32(const void* p) {
    uint32_t a;
    asm("{ .reg .u64 t; cvta.to.shared.u64 t, %1; cvt.u32.u64 %0, t; }" : "=r"(a) : "l"(p));
    return a;
}
__device__ __forceinline__ void cp16(uint32_t dst, const void* src) {
    asm volatile("cp.async.cg.shared.global [%0], [%1], 16;" :: "r"(dst), "l"(src));
}
#define CP_COMMIT()  asm volatile("cp.async.commit_group;" ::: "memory")
#define CP_WAITN(n)  asm volatile("cp.async.wait_group %0;" :: "n"(n) : "memory")

// ---------------------------------------------------------------------------
// k_zero
// ---------------------------------------------------------------------------
__global__ void k_zero(float* out, long long n) {
    long long nq = n >> 2;
    float4* o4 = (float4*)out;
    long long i = (long long)blockIdx.x * blockDim.x + threadIdx.x;
    long long stride = (long long)gridDim.x * blockDim.x;
    for (; i < nq; i += stride) o4[i] = make_float4(0.f, 0.f, 0.f, 0.f);
    if (i == nq)
        for (long long t = nq << 2; t < n; t++) out[t] = 0.f;
}

// ---------------------------------------------------------------------------
// k_prep: Js = sym(J) with zero diag (fp32) + bf16 copy; tile-pair version
// ---------------------------------------------------------------------------
__global__ void k_prep(const float* __restrict__ J) {
    int rem = blockIdx.x;
    int bi = 0;
    while (rem >= NT - bi) { rem -= NT - bi; bi++; }
    int bj = bi + rem;
    __shared__ float ta[32][33];
    __shared__ float tb[32][33];
    int r = threadIdx.y, c = threadIdx.x;
    ta[r][c] = J[(size_t)(bi * 32 + r) * N + (bj * 32 + c)];
    tb[r][c] = J[(size_t)(bj * 32 + r) * N + (bi * 32 + c)];
    __syncthreads();
    {
        int gi = bi * 32 + r, gj = bj * 32 + c;
        float v = (gi == gj) ? 0.0f : 0.5f * (ta[r][c] + tb[c][r]);
        size_t idx = (size_t)gi * N + gj;
        g_Js[idx] = v;
        g_G[idx]  = __float2bfloat16(v);
    }
    if (bi != bj) {
        int gi = bj * 32 + r, gj = bi * 32 + c;
        float v = 0.5f * (tb[r][c] + ta[c][r]);
        size_t idx = (size_t)gi * N + gj;
        g_Js[idx] = v;
        g_G[idx]  = __float2bfloat16(v);
    }
}

// ---------------------------------------------------------------------------
// m0 = tanh(h)
// ---------------------------------------------------------------------------
__global__ void k_minit(const float* __restrict__ h) {
    int i = blockIdx.x * blockDim.x + threadIdx.x;
    if (i < N) g_m[0][i] = tanhf(h[i]);
}

// ---------------------------------------------------------------------------
// bf16 iteration: 4 rows/CTA, 4-stage cp.async pipeline (1024 cols/stage).
// threads 0-127 -> rows 0,1 ; threads 128-255 -> rows 2,3.
// ---------------------------------------------------------------------------
__global__ void __launch_bounds__(256) k_iter_bf16(const float* __restrict__ h, int pin) {
    __shared__ __align__(16) __nv_bfloat16 sj[4][N];   // 32 KB
    int row0 = blockIdx.x * 4;
    const float* mi_v = g_m[pin];
    const float4* mv = (const float4*)mi_v;
    uint32_t sb = smem_u32(&sj[0][0]);
    int tid = threadIdx.x;
    int half = tid >> 7;          // 0 or 1
    int tcol = tid & 127;
    int r0 = half * 2, r1 = r0 + 1;

    // issue all 4 stages (one commit group per stage)
#pragma unroll
    for (int s = 0; s < 4; s++) {
#pragma unroll
        for (int p = 0; p < 2; p++) {
            int r = r0 + p;
            int cc = 128 * s + tcol;                       // 16B chunk (8 bf16)
            cp16(sb + ((uint32_t)r * N + (uint32_t)cc * 8) * 2,
                 g_G + (size_t)(row0 + r) * N + (size_t)cc * 8);
        }
        CP_COMMIT();
    }

    float s1[2] = {0.f, 0.f}, s2[2] = {0.f, 0.f};
#pragma unroll
    for (int s = 0; s < 4; s++) {
        if      (s == 0) CP_WAITN(3);
        else if (s == 1) CP_WAITN(2);
        else if (s == 2) CP_WAITN(1);
        else             CP_WAITN(0);
        __syncthreads();
        int cc = 128 * s + tcol;
        float4 ma = mv[2 * cc], mb = mv[2 * cc + 1];
        float pa[8] = {ma.x, ma.y, ma.z, ma.w, mb.x, mb.y, mb.z, mb.w};
        float pb[8];
#pragma unroll
        for (int e = 0; e < 8; e++) pb[e] = pa[e] * (1.f - pa[e]);
#pragma unroll
        for (int p = 0; p < 2; p++) {
            uint4 v = *(const uint4*)&sj[r0 + p][cc * 8];
            const __nv_bfloat162* b2 = reinterpret_cast<const __nv_bfloat162*>(&v);
            float2 a0 = __bfloat1622float2(b2[0]);
            float2 a1 = __bfloat1622float2(b2[1]);
            float2 a2 = __bfloat1622float2(b2[2]);
            float2 a3 = __bfloat1622float2(b2[3]);
            float av[8] = {a0.x, a0.y, a1.x, a1.y, a2.x, a2.y, a3.x, a3.y};
#pragma unroll
            for (int e = 0; e < 8; e++) {
                s1[p] = fmaf(av[e], pa[e], s1[p]);
                s2[p] = fmaf(av[e] * av[e], pb[e], s2[p]);
            }
        }
    }

    // reduce: warps 0-3 hold rows 0,1 ; warps 4-7 hold rows 2,3
    __shared__ float rs1[8][2], rs2[8][2];
    int lane = tid & 31, w = tid >> 5;
#pragma unroll
    for (int p = 0; p < 2; p++) {
#pragma unroll
        for (int o = 16; o; o >>= 1) {
            s1[p] += __shfl_xor_sync(0xFFFFFFFFu, s1[p], o);
            s2[p] += __shfl_xor_sync(0xFFFFFFFFu, s2[p], o);
        }
        if (lane == 0) { rs1[w][p] = s1[p]; rs2[w][p] = s2[p]; }
    }
    __syncthreads();
    if (tid < 4) {
        int r = tid;                     // row within block
        int wbase = (r >> 1) * 4;        // warps 0-3 or 4-7
        int idx = r & 1;
        float a = 0.f, b = 0.f;
#pragma unroll
        for (int ww = 0; ww < 4; ww++) { a += rs1[wbase + ww][idx]; b += rs2[wbase + ww][idx]; }
        int row = row0 + r;
        float mi = mi_v[row];
        g_m[pin ^ 1][row] = 0.5f * (mi + tanhf(h[row] + a - mi * b));
    }
}

// ---------------------------------------------------------------------------
// fp32 polish iteration: 2 rows/CTA, 4-stage cp.async pipeline
// ---------------------------------------------------------------------------
__global__ void __launch_bounds__(256) k_iter_f32(const float* __restrict__ h, int pin) {
    __shared__ __align__(16) float sj[2][N];            // 32 KB
    int row0 = blockIdx.x * 2;
    const float* mi_v = g_m[pin];
    const float4* mv = (const float4*)mi_v;
    uint32_t sb = smem_u32(&sj[0][0]);
    int tid = threadIdx.x;
    int half = tid >> 7;          // row this thread loads
    int tcol = tid & 127;

    // issue all 4 stages; stage = 1024 cols = 256 float4-chunks per row
#pragma unroll
    for (int s = 0; s < 4; s++) {
#pragma unroll
        for (int p = 0; p < 2; p++) {
            int cc = 256 * s + tcol + 128 * p;             // float4 chunk
            cp16(sb + ((uint32_t)half * N + (uint32_t)cc * 4) * 4,
                 g_Js + (size_t)(row0 + half) * N + (size_t)cc * 4);
        }
        CP_COMMIT();
    }

    float s1[2] = {0.f, 0.f}, s2[2] = {0.f, 0.f};
#pragma unroll
    for (int s = 0; s < 4; s++) {
        if      (s == 0) CP_WAITN(3);
        else if (s == 1) CP_WAITN(2);
        else if (s == 2) CP_WAITN(1);
        else             CP_WAITN(0);
        __syncthreads();
        int cc = 256 * s + tid;
        float4 a0 = *(const float4*)&sj[0][cc * 4];
        float4 a1 = *(const float4*)&sj[1][cc * 4];
        float4 mq = mv[cc];
        float pa[4] = {mq.x, mq.y, mq.z, mq.w};
        float pb[4];
#pragma unroll
        for (int e = 0; e < 4; e++) pb[e] = pa[e] * (1.f - pa[e]);
        float av0[4] = {a0.x, a0.y, a0.z, a0.w};
        float av1[4] = {a1.x, a1.y, a1.z, a1.w};
#pragma unroll
        for (int e = 0; e < 4; e++) {
            s1[0] = fmaf(av0[e], pa[e], s1[0]);
            s2[0] = fmaf(av0[e] * av0[e], pb[e], s2[0]);
            s1[1] = fmaf(av1[e], pa[e], s1[1]);
            s2[1] = fmaf(av1[e] * av1[e], pb[e], s2[1]);
        }
    }

    __shared__ float rs1[8][2], rs2[8][2];
    int lane = tid & 31, w = tid >> 5;
#pragma unroll
    for (int p = 0; p < 2; p++) {
#pragma unroll
        for (int o = 16; o; o >>= 1) {
            s1[p] += __shfl_xor_sync(0xFFFFFFFFu, s1[p], o);
            s2[p] += __shfl_xor_sync(0xFFFFFFFFu, s2[p], o);
        }
        if (lane == 0) { rs1[w][p] = s1[p]; rs2[w][p] = s2[p]; }
    }
    __syncthreads();
    if (tid < 2) {
        int r = tid;
        float a = 0.f, b = 0.f;
#pragma unroll
        for (int ww = 0; ww < 8; ww++) { a += rs1[ww][r]; b += rs2[ww][r]; }
        int row = row0 + r;
        float mi = mi_v[row];
        g_m[pin ^ 1][row] = 0.5f * (mi + tanhf(h[row] + a - mi * b));
    }
}

// ---------------------------------------------------------------------------
// k_vec: finalize m, compute d, w, write m to out
// ---------------------------------------------------------------------------
__global__ void k_vec(float* out, int writeM) {
    int i = blockIdx.x * blockDim.x + threadIdx.x;
    if (i < N) {
        float m = g_m[0][i];
        float d = 1.0f - m * m;
        g_d[i] = d;
        g_w[i] = sqrtf(d);
        if (writeM) out[i] = m;
    }
}

// ---------------------------------------------------------------------------
// k_buildG: G_ij = CINV * w_i * G_ij * w_j (in-place over bf16(Js))
// ---------------------------------------------------------------------------
__global__ void k_buildG() {
    size_t q = (size_t)blockIdx.x * blockDim.x + threadIdx.x;  // 8-elem group
    size_t nq = (size_t)N * N / 8;
    if (q >= nq) return;
    size_t base = q * 8;
    int i = (int)(base >> 12);
    int j = (int)(base & (N - 1));
    uint4 v = *(const uint4*)(g_G + base);
    const __nv_bfloat162* b2 = reinterpret_cast<const __nv_bfloat162*>(&v);
    float s = CINV * g_w[i];
    uint4 outv;
    __nv_bfloat162* o2 = reinterpret_cast<__nv_bfloat162*>(&outv);
#pragma unroll
    for (int e = 0; e < 4; e++) {
        float2 a = __bfloat1622float2(b2[e]);
        float2 r;
        r.x = s * g_w[j + 2 * e]     * a.x;
        r.y = s * g_w[j + 2 * e + 1] * a.y;
        o2[e] = __float22bfloat162_rn(r);
    }
    *(uint4*)(g_G + base) = outv;
}

// ---------------------------------------------------------------------------
// k_gemm: 128x128 upper-triangle tile (bi<=bj), bf16 mma.sync + ldmatrix.
//   pass 1: D = G*G^T       -> H = G + D (bf16)
//   pass 2: D = G*H^T (=S)  -> cov epilogue into out (strictly upper)
// ---------------------------------------------------------------------------
static constexpr int KC  = 32;     // k-chunk
static constexpr int LDT = 40;     // smem row stride (bf16 elems)

__global__ void __launch_bounds__(256) k_gemm(int pass, float* out, long long covBase) {
    __shared__ __align__(16) __nv_bfloat16 sA[2][128 * LDT];
    __shared__ __align__(16) __nv_bfloat16 sB[2][128 * LDT];

    int rem = blockIdx.x;
    int bi = 0;
    while (rem >= NB - bi) { rem -= NB - bi; bi++; }
    int bj = bi + rem;
    int i0 = bi * 128, j0 = bj * 128;

    const __nv_bfloat16* Aop = g_G;
    const __nv_bfloat16* Bop = (pass == 1) ? g_G : g_H;

    int tid = threadIdx.x, lane = tid & 31, wid = tid >> 5;
    int wr = wid >> 2, wc = wid & 3;
    int gID = lane >> 2, tig = lane & 3;

    uint32_t sAu = smem_u32(&sA[0][0]);
    uint32_t sBu = smem_u32(&sB[0][0]);
    const uint32_t BUFB = 128 * LDT * 2;   // bytes per buffer

    // ldmatrix per-lane source offsets (bytes), within a buffer
    int la16 = lane & 15, lkh = lane >> 4;          // A: rows 0-15, k-half
    int lb8  = lane & 7,  lkb = (lane >> 3) & 1;    // B: rows 0-7,  k-half
    uint32_t aoff[4], boff[4];
#pragma unroll
    for (int mi = 0; mi < 4; mi++)
        aoff[mi] = (uint32_t)(((wr * 64 + mi * 16 + la16) * LDT + lkh * 8) * 2);
#pragma unroll
    for (int ni = 0; ni < 4; ni++)
        boff[ni] = (uint32_t)(((wc * 32 + ni * 8 + lb8) * LDT + lkb * 8) * 2);

    float acc[4][4][4];
#pragma unroll
    for (int a = 0; a < 4; a++)
#pragma unroll
        for (int b = 0; b < 4; b++)
#pragma unroll
            for (int c = 0; c < 4; c++) acc[a][b][c] = 0.f;

    int r_[2], g_[2];
    uint32_t soff[2];
#pragma unroll
    for (int t = 0; t < 2; t++) {
        int q = tid + t * 256;
        r_[t] = q >> 2; g_[t] = q & 3;
        soff[t] = (uint32_t)(r_[t] * LDT + g_[t] * 8) * 2;
    }

#pragma unroll
    for (int t = 0; t < 2; t++) {
        cp16(sAu + soff[t], Aop + (size_t)(i0 + r_[t]) * N + g_[t] * 8);
        cp16(sBu + soff[t], Bop + (size_t)(j0 + r_[t]) * N + g_[t] * 8);
    }
    CP_COMMIT();
    CP_WAITN(0);
    __syncthreads();

    const int NCH = N / KC;   // 128
    for (int c = 0; c < NCH; c++) {
        uint32_t bufo = (uint32_t)(c & 1) * BUFB;
        if (c + 1 < NCH) {
            int kc = (c + 1) * KC;
            uint32_t bo = (uint32_t)((c + 1) & 1) * BUFB;
#pragma unroll
            for (int t = 0; t < 2; t++) {
                cp16(sAu + bo + soff[t], Aop + (size_t)(i0 + r_[t]) * N + kc + g_[t] * 8);
                cp16(sBu + bo + soff[t], Bop + (size_t)(j0 + r_[t]) * N + kc + g_[t] * 8);
            }
            CP_COMMIT();
        }
#pragma unroll
        for (int kk = 0; kk < KC; kk += 16) {
            uint32_t af[4][4], bf[4][2];
#pragma unroll
            for (int mi = 0; mi < 4; mi++)
                ldmatrix_x4(af[mi], sAu + bufo + aoff[mi] + kk * 2);
#pragma unroll
            for (int ni = 0; ni < 4; ni++)
                ldmatrix_x2(bf[ni], sBu + bufo + boff[ni] + kk * 2);
#pragma unroll
            for (int mi = 0; mi < 4; mi++)
#pragma unroll
                for (int ni = 0; ni < 4; ni++)
                    mma_bf16(acc[mi][ni], af[mi], bf[ni]);
        }
        if (c + 1 < NCH) CP_WAITN(0);
        __syncthreads();
    }

    // epilogue
#pragma unroll
    for (int mi = 0; mi < 4; mi++) {
#pragma unroll
        for (int r8 = 0; r8 < 2; r8++) {
            int row = i0 + wr * 64 + mi * 16 + gID + r8 * 8;
            if (pass == 1) {
                __nv_bfloat16* dst = g_H + (size_t)row * N;
                const __nv_bfloat16* gsrc = g_G + (size_t)row * N;
#pragma unroll
                for (int ni = 0; ni < 4; ni++) {
                    int col = j0 + wc * 32 + ni * 8 + tig * 2;
                    float2 v;
                    v.x = acc[mi][ni][r8 * 2 + 0] + __bfloat162float(gsrc[col]);
                    v.y = acc[mi][ni][r8 * 2 + 1] + __bfloat162float(gsrc[col + 1]);
                    *(__nv_bfloat162*)(dst + col) = __float22bfloat162_rn(v);
                }
            } else {
                const float* jsrc = g_Js + (size_t)row * N;
                float mrow = g_m[0][row];
                float inv_wr = 1.0f / g_w[row];
#pragma unroll
                for (int ni = 0; ni < 4; ni++) {
                    int col = j0 + wc * 32 + ni * 8 + tig * 2;
#pragma unroll
                    for (int e = 0; e < 2; e++) {
                        int gj = col + e;
                        if (gj > row) {
                            float S = acc[mi][ni][r8 * 2 + e];
                            float cov = mrow * g_m[0][gj]
                                      + CINV * (CINV * jsrc[gj] * g_d[gj] + S * g_w[gj] * inv_wr);
                            out[covBase + (size_t)row * N + gj] = cov;
                        }
                    }
                }
            }
        }
    }
}

// ---------------------------------------------------------------------------
// k_mirrorH: H[r][c] = H[c][r] for r > c
// ---------------------------------------------------------------------------
__global__ void k_mirrorH() {
    int bx = blockIdx.x, by = blockIdx.y;
    if (by < bx) return;
    __shared__ __nv_bfloat16 t[32][33];
    int tx = threadIdx.x, ty = threadIdx.y;
    t[ty][tx] = g_H[(size_t)(bx * 32 + ty) * N + (by * 32 + tx)];
    __syncthreads();
    int dr = by * 32 + ty, dc = bx * 32 + tx;
    if (dr > dc) g_H[(size_t)dr * N + dc] = t[tx][ty];
}

// ---------------------------------------------------------------------------
// kernel_launch
// ---------------------------------------------------------------------------
extern "C" void kernel_launch(void* const* d_in, const int* in_sizes, int n_in,
                              void* d_out, int out_size) {
    const float* h = nullptr;
    const float* J = nullptr;
    for (int i = 0; i < n_in; i++) {
        if (in_sizes[i] == N * N)   J = (const float*)d_in[i];
        else if (in_sizes[i] == N)  h = (const float*)d_in[i];
    }
    float* out = (float*)d_out;
    long long covBase = ((long long)out_size >= (long long)N * N + N) ? N : 0;

    k_zero<<<4096, 256>>>(out, (long long)out_size);
    k_prep<<<NT * (NT + 1) / 2, dim3(32, 32)>>>(J);
    k_minit<<<16, 256>>>(h);
    for (int t = 0; t < TOT_ITERS; t++) {
        if (t < SPLIT) k_iter_bf16<<<N / 4, 256>>>(h, t & 1);
        else           k_iter_f32 <<<N / 2, 256>>>(h, t & 1);
    }
    k_vec<<<16, 256>>>(out, covBase > 0 ? 1 : 0);
    k_buildG<<<(int)(((size_t)N * N / 8 + 255) / 256), 256>>>();
    k_gemm<<<NB * (NB + 1) / 2, 256>>>(1, out, covBase);
    k_mirrorH<<<dim3(N / 32, N / 32), dim3(32, 32)>>>();
    k_gemm<<<NB * (NB + 1) / 2, 256>>>(2, out, covBase);
}

// round 9
// speedup vs baseline: 2.1359x; 1.0694x over previous
#include <cuda_runtime.h>
#include <cuda_bf16.h>
#include <cstdint>
#include <cstddef>

static constexpr int   N     = 4096;
static constexpr int   NB    = 32;            // 128-tiles per side
static constexpr int   NT    = 128;           // 32-tiles per side
static constexpr int   TOT_ITERS = 18;        // 14 bf16 + 4 fp32 polish (even -> m ends in g_m[0])
static constexpr int   SPLIT = 14;
static constexpr float CINV  = 1.0f / 1.000001f;

// ---------------------------------------------------------------------------
// Device scratch (allocation-free rule: __device__ globals)
// ---------------------------------------------------------------------------
static __device__ float         g_Js[(size_t)N * N];  // 64 MB symmetrized J (fp32)
static __device__ __nv_bfloat16 g_G [(size_t)N * N];  // 32 MB: Js(bf16) during iters, then G
static __device__ __nv_bfloat16 g_H [(size_t)N * N];  // 32 MB: H = G + G^2
static __device__ float         g_m [2][N];
static __device__ float         g_d [N];
static __device__ float         g_w [N];

// ---------------------------------------------------------------------------
// PTX wrappers (all baseline PTX: sm_75/sm_80 features, compute_103-safe)
// ---------------------------------------------------------------------------
__device__ __forceinline__ void mma_bf16(float* c, const uint32_t* a, const uint32_t* b) {
    asm volatile(
        "mma.sync.aligned.m16n8k16.row.col.f32.bf16.bf16.f32 "
        "{%0,%1,%2,%3}, {%4,%5,%6,%7}, {%8,%9}, {%0,%1,%2,%3};\n"
        : "+f"(c[0]), "+f"(c[1]), "+f"(c[2]), "+f"(c[3])
        : "r"(a[0]), "r"(a[1]), "r"(a[2]), "r"(a[3]), "r"(b[0]), "r"(b[1]));
}
__device__ __forceinline__ void ldmatrix_x4(uint32_t* r, uint32_t addr) {
    asm volatile("ldmatrix.sync.aligned.m8n8.x4.shared.b16 {%0,%1,%2,%3}, [%4];"
                 : "=r"(r[0]), "=r"(r[1]), "=r"(r[2]), "=r"(r[3]) : "r"(addr));
}
__device__ __forceinline__ void ldmatrix_x2(uint32_t* r, uint32_t addr) {
    asm volatile("ldmatrix.sync.aligned.m8n8.x2.shared.b16 {%0,%1}, [%2];"
                 : "=r"(r[0]), "=r"(r[1]) : "r"(addr));
}
__device__ __forceinline__ uint32_t smem_u32(const void* p) {
    uint32_t a;
    asm("{ .reg .u64 t; cvta.to.shared.u64 t, %1; cvt.u32.u64 %0, t; }" : "=r"(a) : "l"(p));
    return a;
}
__device__ __forceinline__ void cp16(uint32_t dst, const void* src) {
    asm volatile("cp.async.cg.shared.global [%0], [%1], 16;" :: "r"(dst), "l"(src));
}
#define CP_COMMIT()  asm volatile("cp.async.commit_group;" ::: "memory")
#define CP_WAITN(n)  asm volatile("cp.async.wait_group %0;" :: "n"(n) : "memory")

// ---------------------------------------------------------------------------
// k_zero
// ---------------------------------------------------------------------------
__global__ void k_zero(float* out, long long n) {
    long long nq = n >> 2;
    float4* o4 = (float4*)out;
    long long i = (long long)blockIdx.x * blockDim.x + threadIdx.x;
    long long stride = (long long)gridDim.x * blockDim.x;
    for (; i < nq; i += stride) o4[i] = make_float4(0.f, 0.f, 0.f, 0.f);
    if (i == nq)
        for (long long t = nq << 2; t < n; t++) out[t] = 0.f;
}

// ---------------------------------------------------------------------------
// k_prep: Js = sym(J) with zero diag (fp32) + bf16 copy; tile-pair version
// ---------------------------------------------------------------------------
__global__ void k_prep(const float* __restrict__ J) {
    int rem = blockIdx.x;
    int bi = 0;
    while (rem >= NT - bi) { rem -= NT - bi; bi++; }
    int bj = bi + rem;
    __shared__ float ta[32][33];
    __shared__ float tb[32][33];
    int r = threadIdx.y, c = threadIdx.x;
    ta[r][c] = J[(size_t)(bi * 32 + r) * N + (bj * 32 + c)];
    tb[r][c] = J[(size_t)(bj * 32 + r) * N + (bi * 32 + c)];
    __syncthreads();
    {
        int gi = bi * 32 + r, gj = bj * 32 + c;
        float v = (gi == gj) ? 0.0f : 0.5f * (ta[r][c] + tb[c][r]);
        size_t idx = (size_t)gi * N + gj;
        g_Js[idx] = v;
        g_G[idx]  = __float2bfloat16(v);
    }
    if (bi != bj) {
        int gi = bj * 32 + r, gj = bi * 32 + c;
        float v = 0.5f * (tb[r][c] + ta[c][r]);
        size_t idx = (size_t)gi * N + gj;
        g_Js[idx] = v;
        g_G[idx]  = __float2bfloat16(v);
    }
}

// ---------------------------------------------------------------------------
// m0 = tanh(h)
// ---------------------------------------------------------------------------
__global__ void k_minit(const float* __restrict__ h) {
    int i = blockIdx.x * blockDim.x + threadIdx.x;
    if (i < N) g_m[0][i] = tanhf(h[i]);
}

// ---------------------------------------------------------------------------
// bf16 iteration: 4 rows/CTA, 4-stage cp.async pipeline, BARRIER-FREE stages
// (each thread consumes exactly the smem bytes it copied; wait_group is
//  per-thread). threads 0-127 -> rows 0,1 ; threads 128-255 -> rows 2,3.
// ---------------------------------------------------------------------------
__global__ void __launch_bounds__(256) k_iter_bf16(const float* __restrict__ h, int pin) {
    __shared__ __align__(16) __nv_bfloat16 sj[4][N];   // 32 KB
    int row0 = blockIdx.x * 4;
    const float* mi_v = g_m[pin];
    const float4* mv = (const float4*)mi_v;
    uint32_t sb = smem_u32(&sj[0][0]);
    int tid = threadIdx.x;
    int half = tid >> 7;          // 0 or 1
    int tcol = tid & 127;
    int r0 = half * 2;

    // issue all 4 stages (one commit group per stage)
#pragma unroll
    for (int s = 0; s < 4; s++) {
#pragma unroll
        for (int p = 0; p < 2; p++) {
            int r = r0 + p;
            int cc = 128 * s + tcol;                       // 16B chunk (8 bf16)
            cp16(sb + ((uint32_t)r * N + (uint32_t)cc * 8) * 2,
                 g_G + (size_t)(row0 + r) * N + (size_t)cc * 8);
        }
        CP_COMMIT();
    }

    float s1[2] = {0.f, 0.f}, s2[2] = {0.f, 0.f};
#pragma unroll
    for (int s = 0; s < 4; s++) {
        if      (s == 0) CP_WAITN(3);
        else if (s == 1) CP_WAITN(2);
        else if (s == 2) CP_WAITN(1);
        else             CP_WAITN(0);
        int cc = 128 * s + tcol;
        float4 ma = mv[2 * cc], mb = mv[2 * cc + 1];
        float pa[8] = {ma.x, ma.y, ma.z, ma.w, mb.x, mb.y, mb.z, mb.w};
        float pb[8];
#pragma unroll
        for (int e = 0; e < 8; e++) pb[e] = pa[e] * (1.f - pa[e]);
#pragma unroll
        for (int p = 0; p < 2; p++) {
            uint4 v = *(const uint4*)&sj[r0 + p][cc * 8];
            const __nv_bfloat162* b2 = reinterpret_cast<const __nv_bfloat162*>(&v);
            float2 a0 = __bfloat1622float2(b2[0]);
            float2 a1 = __bfloat1622float2(b2[1]);
            float2 a2 = __bfloat1622float2(b2[2]);
            float2 a3 = __bfloat1622float2(b2[3]);
            float av[8] = {a0.x, a0.y, a1.x, a1.y, a2.x, a2.y, a3.x, a3.y};
#pragma unroll
            for (int e = 0; e < 8; e++) {
                s1[p] = fmaf(av[e], pa[e], s1[p]);
                s2[p] = fmaf(av[e] * av[e], pb[e], s2[p]);
            }
        }
    }

    // reduce: warps 0-3 hold rows 0,1 ; warps 4-7 hold rows 2,3
    __shared__ float rs1[8][2], rs2[8][2];
    int lane = tid & 31, w = tid >> 5;
#pragma unroll
    for (int p = 0; p < 2; p++) {
#pragma unroll
        for (int o = 16; o; o >>= 1) {
            s1[p] += __shfl_xor_sync(0xFFFFFFFFu, s1[p], o);
            s2[p] += __shfl_xor_sync(0xFFFFFFFFu, s2[p], o);
        }
        if (lane == 0) { rs1[w][p] = s1[p]; rs2[w][p] = s2[p]; }
    }
    __syncthreads();
    if (tid < 4) {
        int r = tid;                     // row within block
        int wbase = (r >> 1) * 4;        // warps 0-3 or 4-7
        int idx = r & 1;
        float a = 0.f, b = 0.f;
#pragma unroll
        for (int ww = 0; ww < 4; ww++) { a += rs1[wbase + ww][idx]; b += rs2[wbase + ww][idx]; }
        int row = row0 + r;
        float mi = mi_v[row];
        g_m[pin ^ 1][row] = 0.5f * (mi + tanhf(h[row] + a - mi * b));
    }
}

// ---------------------------------------------------------------------------
// fp32 polish: 2 rows/CTA, barrier-free 4-stage pipeline; each thread works
// ONLY on the row it loaded (half). warps 0-3 -> row 0, warps 4-7 -> row 1.
// ---------------------------------------------------------------------------
__global__ void __launch_bounds__(256) k_iter_f32(const float* __restrict__ h, int pin) {
    __shared__ __align__(16) float sj[2][N];            // 32 KB
    int row0 = blockIdx.x * 2;
    const float* mi_v = g_m[pin];
    const float4* mv = (const float4*)mi_v;
    uint32_t sb = smem_u32(&sj[0][0]);
    int tid = threadIdx.x;
    int half = tid >> 7;          // row this thread loads AND computes
    int tcol = tid & 127;

    // issue 4 stages; stage = 256 float4-chunks per row; thread owns chunks
    // {256s+tcol, 256s+tcol+128}
#pragma unroll
    for (int s = 0; s < 4; s++) {
#pragma unroll
        for (int p = 0; p < 2; p++) {
            int cc = 256 * s + tcol + 128 * p;
            cp16(sb + ((uint32_t)half * N + (uint32_t)cc * 4) * 4,
                 g_Js + (size_t)(row0 + half) * N + (size_t)cc * 4);
        }
        CP_COMMIT();
    }

    float s1 = 0.f, s2 = 0.f;
#pragma unroll
    for (int s = 0; s < 4; s++) {
        if      (s == 0) CP_WAITN(3);
        else if (s == 1) CP_WAITN(2);
        else if (s == 2) CP_WAITN(1);
        else             CP_WAITN(0);
#pragma unroll
        for (int p = 0; p < 2; p++) {
            int cc = 256 * s + tcol + 128 * p;
            float4 a = *(const float4*)&sj[half][cc * 4];
            float4 mq = mv[cc];
            float pa[4] = {mq.x, mq.y, mq.z, mq.w};
            float av[4] = {a.x, a.y, a.z, a.w};
#pragma unroll
            for (int e = 0; e < 4; e++) {
                float pb = pa[e] * (1.f - pa[e]);
                s1 = fmaf(av[e], pa[e], s1);
                s2 = fmaf(av[e] * av[e], pb, s2);
            }
        }
    }

    // reduce within each half (4 warps per row)
    __shared__ float rs1[8], rs2[8];
    int lane = tid & 31, w = tid >> 5;
#pragma unroll
    for (int o = 16; o; o >>= 1) {
        s1 += __shfl_xor_sync(0xFFFFFFFFu, s1, o);
        s2 += __shfl_xor_sync(0xFFFFFFFFu, s2, o);
    }
    if (lane == 0) { rs1[w] = s1; rs2[w] = s2; }
    __syncthreads();
    if (tid < 2) {
        int r = tid;
        float a = 0.f, b = 0.f;
#pragma unroll
        for (int ww = 0; ww < 4; ww++) { a += rs1[r * 4 + ww]; b += rs2[r * 4 + ww]; }
        int row = row0 + r;
        float mi = mi_v[row];
        g_m[pin ^ 1][row] = 0.5f * (mi + tanhf(h[row] + a - mi * b));
    }
}

// ---------------------------------------------------------------------------
// k_vec: finalize m, compute d, w, write m to out
// ---------------------------------------------------------------------------
__global__ void k_vec(float* out, int writeM) {
    int i = blockIdx.x * blockDim.x + threadIdx.x;
    if (i < N) {
        float m = g_m[0][i];
        float d = 1.0f - m * m;
        g_d[i] = d;
        g_w[i] = sqrtf(d);
        if (writeM) out[i] = m;
    }
}

// ---------------------------------------------------------------------------
// k_buildG: G_ij = CINV * w_i * G_ij * w_j (in-place over bf16(Js))
// ---------------------------------------------------------------------------
__global__ void k_buildG() {
    size_t q = (size_t)blockIdx.x * blockDim.x + threadIdx.x;  // 8-elem group
    size_t nq = (size_t)N * N / 8;
    if (q >= nq) return;
    size_t base = q * 8;
    int i = (int)(base >> 12);
    int j = (int)(base & (N - 1));
    uint4 v = *(const uint4*)(g_G + base);
    const __nv_bfloat162* b2 = reinterpret_cast<const __nv_bfloat162*>(&v);
    float s = CINV * g_w[i];
    uint4 outv;
    __nv_bfloat162* o2 = reinterpret_cast<__nv_bfloat162*>(&outv);
#pragma unroll
    for (int e = 0; e < 4; e++) {
        float2 a = __bfloat1622float2(b2[e]);
        float2 r;
        r.x = s * g_w[j + 2 * e]     * a.x;
        r.y = s * g_w[j + 2 * e + 1] * a.y;
        o2[e] = __float22bfloat162_rn(r);
    }
    *(uint4*)(g_G + base) = outv;
}

// ---------------------------------------------------------------------------
// k_gemm: 128x128 upper-triangle tile (bi<=bj), bf16 mma.sync + ldmatrix.
//   pass 1: D = G*G^T       -> H = G + D (bf16)
//   pass 2: D = G*H^T (=S)  -> cov epilogue into out (strictly upper)
// ---------------------------------------------------------------------------
static constexpr int KC  = 32;     // k-chunk
static constexpr int LDT = 40;     // smem row stride (bf16 elems)

__global__ void __launch_bounds__(256) k_gemm(int pass, float* out, long long covBase) {
    __shared__ __align__(16) __nv_bfloat16 sA[2][128 * LDT];
    __shared__ __align__(16) __nv_bfloat16 sB[2][128 * LDT];

    int rem = blockIdx.x;
    int bi = 0;
    while (rem >= NB - bi) { rem -= NB - bi; bi++; }
    int bj = bi + rem;
    int i0 = bi * 128, j0 = bj * 128;

    const __nv_bfloat16* Aop = g_G;
    const __nv_bfloat16* Bop = (pass == 1) ? g_G : g_H;

    int tid = threadIdx.x, lane = tid & 31, wid = tid >> 5;
    int wr = wid >> 2, wc = wid & 3;
    int gID = lane >> 2, tig = lane & 3;

    uint32_t sAu = smem_u32(&sA[0][0]);
    uint32_t sBu = smem_u32(&sB[0][0]);
    const uint32_t BUFB = 128 * LDT * 2;   // bytes per buffer

    int la16 = lane & 15, lkh = lane >> 4;          // A: rows 0-15, k-half
    int lb8  = lane & 7,  lkb = (lane >> 3) & 1;    // B: rows 0-7,  k-half
    uint32_t aoff[4], boff[4];
#pragma unroll
    for (int mi = 0; mi < 4; mi++)
        aoff[mi] = (uint32_t)(((wr * 64 + mi * 16 + la16) * LDT + lkh * 8) * 2);
#pragma unroll
    for (int ni = 0; ni < 4; ni++)
        boff[ni] = (uint32_t)(((wc * 32 + ni * 8 + lb8) * LDT + lkb * 8) * 2);

    float acc[4][4][4];
#pragma unroll
    for (int a = 0; a < 4; a++)
#pragma unroll
        for (int b = 0; b < 4; b++)
#pragma unroll
            for (int c = 0; c < 4; c++) acc[a][b][c] = 0.f;

    int r_[2], g_[2];
    uint32_t soff[2];
#pragma unroll
    for (int t = 0; t < 2; t++) {
        int q = tid + t * 256;
        r_[t] = q >> 2; g_[t] = q & 3;
        soff[t] = (uint32_t)(r_[t] * LDT + g_[t] * 8) * 2;
    }

#pragma unroll
    for (int t = 0; t < 2; t++) {
        cp16(sAu + soff[t], Aop + (size_t)(i0 + r_[t]) * N + g_[t] * 8);
        cp16(sBu + soff[t], Bop + (size_t)(j0 + r_[t]) * N + g_[t] * 8);
    }
    CP_COMMIT();
    CP_WAITN(0);
    __syncthreads();

    const int NCH = N / KC;   // 128
    for (int c = 0; c < NCH; c++) {
        uint32_t bufo = (uint32_t)(c & 1) * BUFB;
        if (c + 1 < NCH) {
            int kc = (c + 1) * KC;
            uint32_t bo = (uint32_t)((c + 1) & 1) * BUFB;
#pragma unroll
            for (int t = 0; t < 2; t++) {
                cp16(sAu + bo + soff[t], Aop + (size_t)(i0 + r_[t]) * N + kc + g_[t] * 8);
                cp16(sBu + bo + soff[t], Bop + (size_t)(j0 + r_[t]) * N + kc + g_[t] * 8);
            }
            CP_COMMIT();
        }
#pragma unroll
        for (int kk = 0; kk < KC; kk += 16) {
            uint32_t af[4][4], bf[4][2];
#pragma unroll
            for (int mi = 0; mi < 4; mi++)
                ldmatrix_x4(af[mi], sAu + bufo + aoff[mi] + kk * 2);
#pragma unroll
            for (int ni = 0; ni < 4; ni++)
                ldmatrix_x2(bf[ni], sBu + bufo + boff[ni] + kk * 2);
#pragma unroll
            for (int mi = 0; mi < 4; mi++)
#pragma unroll
                for (int ni = 0; ni < 4; ni++)
                    mma_bf16(acc[mi][ni], af[mi], bf[ni]);
        }
        if (c + 1 < NCH) CP_WAITN(0);
        __syncthreads();
    }

    // epilogue
#pragma unroll
    for (int mi = 0; mi < 4; mi++) {
#pragma unroll
        for (int r8 = 0; r8 < 2; r8++) {
            int row = i0 + wr * 64 + mi * 16 + gID + r8 * 8;
            if (pass == 1) {
                __nv_bfloat16* dst = g_H + (size_t)row * N;
                const __nv_bfloat16* gsrc = g_G + (size_t)row * N;
#pragma unroll
                for (int ni = 0; ni < 4; ni++) {
                    int col = j0 + wc * 32 + ni * 8 + tig * 2;
                    float2 v;
                    v.x = acc[mi][ni][r8 * 2 + 0] + __bfloat162float(gsrc[col]);
                    v.y = acc[mi][ni][r8 * 2 + 1] + __bfloat162float(gsrc[col + 1]);
                    *(__nv_bfloat162*)(dst + col) = __float22bfloat162_rn(v);
                }
            } else {
                const float* jsrc = g_Js + (size_t)row * N;
                float mrow = g_m[0][row];
                float inv_wr = 1.0f / g_w[row];
#pragma unroll
                for (int ni = 0; ni < 4; ni++) {
                    int col = j0 + wc * 32 + ni * 8 + tig * 2;
#pragma unroll
                    for (int e = 0; e < 2; e++) {
                        int gj = col + e;
                        if (gj > row) {
                            float S = acc[mi][ni][r8 * 2 + e];
                            float cov = mrow * g_m[0][gj]
                                      + CINV * (CINV * jsrc[gj] * g_d[gj] + S * g_w[gj] * inv_wr);
                            out[covBase + (size_t)row * N + gj] = cov;
                        }
                    }
                }
            }
        }
    }
}

// ---------------------------------------------------------------------------
// k_mirrorH: H[r][c] = H[c][r] for r > c
// ---------------------------------------------------------------------------
__global__ void k_mirrorH() {
    int bx = blockIdx.x, by = blockIdx.y;
    if (by < bx) return;
    __shared__ __nv_bfloat16 t[32][33];
    int tx = threadIdx.x, ty = threadIdx.y;
    t[ty][tx] = g_H[(size_t)(bx * 32 + ty) * N + (by * 32 + tx)];
    __syncthreads();
    int dr = by * 32 + ty, dc = bx * 32 + tx;
    if (dr > dc) g_H[(size_t)dr * N + dc] = t[tx][ty];
}

// ---------------------------------------------------------------------------
// kernel_launch
// ---------------------------------------------------------------------------
extern "C" void kernel_launch(void* const* d_in, const int* in_sizes, int n_in,
                              void* d_out, int out_size) {
    const float* h = nullptr;
    const float* J = nullptr;
    for (int i = 0; i < n_in; i++) {
        if (in_sizes[i] == N * N)   J = (const float*)d_in[i];
        else if (in_sizes[i] == N)  h = (const float*)d_in[i];
    }
    float* out = (float*)d_out;
    long long covBase = ((long long)out_size >= (long long)N * N + N) ? N : 0;

    k_zero<<<4096, 256>>>(out, (long long)out_size);
    k_prep<<<NT * (NT + 1) / 2, dim3(32, 32)>>>(J);
    k_minit<<<16, 256>>>(h);
    for (int t = 0; t < TOT_ITERS; t++) {
        if (t < SPLIT) k_iter_bf16<<<N / 4, 256>>>(h, t & 1);
        else           k_iter_f32 <<<N / 2, 256>>>(h, t & 1);
    }
    k_vec<<<16, 256>>>(out, covBase > 0 ? 1 : 0);
    k_buildG<<<(int)(((size_t)N * N / 8 + 255) / 256), 256>>>();
    k_gemm<<<NB * (NB + 1) / 2, 256>>>(1, out, covBase);
    k_mirrorH<<<dim3(N / 32, N / 32), dim3(32, 32)>>>();
    k_gemm<<<NB * (NB + 1) / 2, 256>>>(2, out, covBase);
}

// round 11
// speedup vs baseline: 2.4066x; 1.1267x over previous
#include <cuda_runtime.h>
#include <cuda_bf16.h>
#include <cstdint>
#include <cstddef>

static constexpr int   N     = 4096;
static constexpr int   NB    = 32;            // 128-tiles per side
static constexpr int   NT    = 128;           // 32-tiles per side
static constexpr int   TOT_ITERS = 16;        // 12 bf16 + 4 fp32 polish (even -> m ends in g_m[0])
static constexpr int   SPLIT = 12;
static constexpr float CINV  = 1.0f / 1.000001f;

// ---------------------------------------------------------------------------
// Device scratch (allocation-free rule: __device__ globals)
// ---------------------------------------------------------------------------
static __device__ float         g_Js[(size_t)N * N];  // 64 MB symmetrized J (fp32)
static __device__ __nv_bfloat16 g_G [(size_t)N * N];  // 32 MB: Js(bf16) during iters, then G
static __device__ __nv_bfloat16 g_H [(size_t)N * N];  // 32 MB: H = G + G^2
static __device__ float         g_m [2][N];
static __device__ float         g_d [N];
static __device__ float         g_w [N];

// ---------------------------------------------------------------------------
// PTX wrappers (all baseline PTX: sm_75/sm_80 features, compute_103-safe)
// ---------------------------------------------------------------------------
__device__ __forceinline__ void mma_bf16(float* c, const uint32_t* a, const uint32_t* b) {
    asm volatile(
        "mma.sync.aligned.m16n8k16.row.col.f32.bf16.bf16.f32 "
        "{%0,%1,%2,%3}, {%4,%5,%6,%7}, {%8,%9}, {%0,%1,%2,%3};\n"
        : "+f"(c[0]), "+f"(c[1]), "+f"(c[2]), "+f"(c[3])
        : "r"(a[0]), "r"(a[1]), "r"(a[2]), "r"(a[3]), "r"(b[0]), "r"(b[1]));
}
__device__ __forceinline__ void ldmatrix_x4(uint32_t* r, uint32_t addr) {
    asm volatile("ldmatrix.sync.aligned.m8n8.x4.shared.b16 {%0,%1,%2,%3}, [%4];"
                 : "=r"(r[0]), "=r"(r[1]), "=r"(r[2]), "=r"(r[3]) : "r"(addr));
}
__device__ __forceinline__ uint32_t smem_u32(const void* p) {
    uint32_t a;
    asm("{ .reg .u64 t; cvta.to.shared.u64 t, %1; cvt.u32.u64 %0, t; }" : "=r"(a) : "l"(p));
    return a;
}
__device__ __forceinline__ void cp16(uint32_t dst, const void* src) {
    asm volatile("cp.async.cg.shared.global [%0], [%1], 16;" :: "r"(dst), "l"(src));
}
#define CP_COMMIT()  asm volatile("cp.async.commit_group;" ::: "memory")
#define CP_WAITN(n)  asm volatile("cp.async.wait_group %0;" :: "n"(n) : "memory")

// ---------------------------------------------------------------------------
// k_zero
// ---------------------------------------------------------------------------
__global__ void k_zero(float* out, long long n) {
    long long nq = n >> 2;
    float4* o4 = (float4*)out;
    long long i = (long long)blockIdx.x * blockDim.x + threadIdx.x;
    long long stride = (long long)gridDim.x * blockDim.x;
    for (; i < nq; i += stride) o4[i] = make_float4(0.f, 0.f, 0.f, 0.f);
    if (i == nq)
        for (long long t = nq << 2; t < n; t++) out[t] = 0.f;
}

// ---------------------------------------------------------------------------
// k_prep: Js = sym(J) with zero diag (fp32) + bf16 copy; tile-pair version
// ---------------------------------------------------------------------------
__global__ void k_prep(const float* __restrict__ J) {
    int rem = blockIdx.x;
    int bi = 0;
    while (rem >= NT - bi) { rem -= NT - bi; bi++; }
    int bj = bi + rem;
    __shared__ float ta[32][33];
    __shared__ float tb[32][33];
    int r = threadIdx.y, c = threadIdx.x;
    ta[r][c] = J[(size_t)(bi * 32 + r) * N + (bj * 32 + c)];
    tb[r][c] = J[(size_t)(bj * 32 + r) * N + (bi * 32 + c)];
    __syncthreads();
    {
        int gi = bi * 32 + r, gj = bj * 32 + c;
        float v = (gi == gj) ? 0.0f : 0.5f * (ta[r][c] + tb[c][r]);
        size_t idx = (size_t)gi * N + gj;
        g_Js[idx] = v;
        g_G[idx]  = __float2bfloat16(v);
    }
    if (bi != bj) {
        int gi = bj * 32 + r, gj = bi * 32 + c;
        float v = 0.5f * (tb[r][c] + ta[c][r]);
        size_t idx = (size_t)gi * N + gj;
        g_Js[idx] = v;
        g_G[idx]  = __float2bfloat16(v);
    }
}

// ---------------------------------------------------------------------------
// m0 = tanh(h)
// ---------------------------------------------------------------------------
__global__ void k_minit(const float* __restrict__ h) {
    int i = blockIdx.x * blockDim.x + threadIdx.x;
    if (i < N) g_m[0][i] = tanhf(h[i]);
}

// ---------------------------------------------------------------------------
// bf16 iteration: 4 rows/CTA, 4-stage cp.async pipeline, BARRIER-FREE stages
// ---------------------------------------------------------------------------
__global__ void __launch_bounds__(256) k_iter_bf16(const float* __restrict__ h, int pin) {
    __shared__ __align__(16) __nv_bfloat16 sj[4][N];   // 32 KB
    int row0 = blockIdx.x * 4;
    const float* mi_v = g_m[pin];
    const float4* mv = (const float4*)mi_v;
    uint32_t sb = smem_u32(&sj[0][0]);
    int tid = threadIdx.x;
    int half = tid >> 7;          // 0 or 1
    int tcol = tid & 127;
    int r0 = half * 2;

#pragma unroll
    for (int s = 0; s < 4; s++) {
#pragma unroll
        for (int p = 0; p < 2; p++) {
            int r = r0 + p;
            int cc = 128 * s + tcol;                       // 16B chunk (8 bf16)
            cp16(sb + ((uint32_t)r * N + (uint32_t)cc * 8) * 2,
                 g_G + (size_t)(row0 + r) * N + (size_t)cc * 8);
        }
        CP_COMMIT();
    }

    float s1[2] = {0.f, 0.f}, s2[2] = {0.f, 0.f};
#pragma unroll
    for (int s = 0; s < 4; s++) {
        if      (s == 0) CP_WAITN(3);
        else if (s == 1) CP_WAITN(2);
        else if (s == 2) CP_WAITN(1);
        else             CP_WAITN(0);
        int cc = 128 * s + tcol;
        float4 ma = mv[2 * cc], mb = mv[2 * cc + 1];
        float pa[8] = {ma.x, ma.y, ma.z, ma.w, mb.x, mb.y, mb.z, mb.w};
        float pb[8];
#pragma unroll
        for (int e = 0; e < 8; e++) pb[e] = pa[e] * (1.f - pa[e]);
#pragma unroll
        for (int p = 0; p < 2; p++) {
            uint4 v = *(const uint4*)&sj[r0 + p][cc * 8];
            const __nv_bfloat162* b2 = reinterpret_cast<const __nv_bfloat162*>(&v);
            float2 a0 = __bfloat1622float2(b2[0]);
            float2 a1 = __bfloat1622float2(b2[1]);
            float2 a2 = __bfloat1622float2(b2[2]);
            float2 a3 = __bfloat1622float2(b2[3]);
            float av[8] = {a0.x, a0.y, a1.x, a1.y, a2.x, a2.y, a3.x, a3.y};
#pragma unroll
            for (int e = 0; e < 8; e++) {
                s1[p] = fmaf(av[e], pa[e], s1[p]);
                s2[p] = fmaf(av[e] * av[e], pb[e], s2[p]);
            }
        }
    }

    __shared__ float rs1[8][2], rs2[8][2];
    int lane = tid & 31, w = tid >> 5;
#pragma unroll
    for (int p = 0; p < 2; p++) {
#pragma unroll
        for (int o = 16; o; o >>= 1) {
            s1[p] += __shfl_xor_sync(0xFFFFFFFFu, s1[p], o);
            s2[p] += __shfl_xor_sync(0xFFFFFFFFu, s2[p], o);
        }
        if (lane == 0) { rs1[w][p] = s1[p]; rs2[w][p] = s2[p]; }
    }
    __syncthreads();
    if (tid < 4) {
        int r = tid;
        int wbase = (r >> 1) * 4;
        int idx = r & 1;
        float a = 0.f, b = 0.f;
#pragma unroll
        for (int ww = 0; ww < 4; ww++) { a += rs1[wbase + ww][idx]; b += rs2[wbase + ww][idx]; }
        int row = row0 + r;
        float mi = mi_v[row];
        g_m[pin ^ 1][row] = 0.5f * (mi + tanhf(h[row] + a - mi * b));
    }
}

// ---------------------------------------------------------------------------
// fp32 polish: 2 rows/CTA, barrier-free 4-stage pipeline
// ---------------------------------------------------------------------------
__global__ void __launch_bounds__(256) k_iter_f32(const float* __restrict__ h, int pin) {
    __shared__ __align__(16) float sj[2][N];            // 32 KB
    int row0 = blockIdx.x * 2;
    const float* mi_v = g_m[pin];
    const float4* mv = (const float4*)mi_v;
    uint32_t sb = smem_u32(&sj[0][0]);
    int tid = threadIdx.x;
    int half = tid >> 7;
    int tcol = tid & 127;

#pragma unroll
    for (int s = 0; s < 4; s++) {
#pragma unroll
        for (int p = 0; p < 2; p++) {
            int cc = 256 * s + tcol + 128 * p;
            cp16(sb + ((uint32_t)half * N + (uint32_t)cc * 4) * 4,
                 g_Js + (size_t)(row0 + half) * N + (size_t)cc * 4);
        }
        CP_COMMIT();
    }

    float s1 = 0.f, s2 = 0.f;
#pragma unroll
    for (int s = 0; s < 4; s++) {
        if      (s == 0) CP_WAITN(3);
        else if (s == 1) CP_WAITN(2);
        else if (s == 2) CP_WAITN(1);
        else             CP_WAITN(0);
#pragma unroll
        for (int p = 0; p < 2; p++) {
            int cc = 256 * s + tcol + 128 * p;
            float4 a = *(const float4*)&sj[half][cc * 4];
            float4 mq = mv[cc];
            float pa[4] = {mq.x, mq.y, mq.z, mq.w};
            float av[4] = {a.x, a.y, a.z, a.w};
#pragma unroll
            for (int e = 0; e < 4; e++) {
                float pb = pa[e] * (1.f - pa[e]);
                s1 = fmaf(av[e], pa[e], s1);
                s2 = fmaf(av[e] * av[e], pb, s2);
            }
        }
    }

    __shared__ float rs1[8], rs2[8];
    int lane = tid & 31, w = tid >> 5;
#pragma unroll
    for (int o = 16; o; o >>= 1) {
        s1 += __shfl_xor_sync(0xFFFFFFFFu, s1, o);
        s2 += __shfl_xor_sync(0xFFFFFFFFu, s2, o);
    }
    if (lane == 0) { rs1[w] = s1; rs2[w] = s2; }
    __syncthreads();
    if (tid < 2) {
        int r = tid;
        float a = 0.f, b = 0.f;
#pragma unroll
        for (int ww = 0; ww < 4; ww++) { a += rs1[r * 4 + ww]; b += rs2[r * 4 + ww]; }
        int row = row0 + r;
        float mi = mi_v[row];
        g_m[pin ^ 1][row] = 0.5f * (mi + tanhf(h[row] + a - mi * b));
    }
}

// ---------------------------------------------------------------------------
// k_vec: finalize m, compute d, w, write m to out
// ---------------------------------------------------------------------------
__global__ void k_vec(float* out, int writeM) {
    int i = blockIdx.x * blockDim.x + threadIdx.x;
    if (i < N) {
        float m = g_m[0][i];
        float d = 1.0f - m * m;
        g_d[i] = d;
        g_w[i] = sqrtf(d);
        if (writeM) out[i] = m;
    }
}

// ---------------------------------------------------------------------------
// k_buildG: G_ij = CINV * w_i * G_ij * w_j (in-place over bf16(Js))
// ---------------------------------------------------------------------------
__global__ void k_buildG() {
    size_t q = (size_t)blockIdx.x * blockDim.x + threadIdx.x;  // 8-elem group
    size_t nq = (size_t)N * N / 8;
    if (q >= nq) return;
    size_t base = q * 8;
    int i = (int)(base >> 12);
    int j = (int)(base & (N - 1));
    uint4 v = *(const uint4*)(g_G + base);
    const __nv_bfloat162* b2 = reinterpret_cast<const __nv_bfloat162*>(&v);
    float s = CINV * g_w[i];
    uint4 outv;
    __nv_bfloat162* o2 = reinterpret_cast<__nv_bfloat162*>(&outv);
#pragma unroll
    for (int e = 0; e < 4; e++) {
        float2 a = __bfloat1622float2(b2[e]);
        float2 r;
        r.x = s * g_w[j + 2 * e]     * a.x;
        r.y = s * g_w[j + 2 * e + 1] * a.y;
        o2[e] = __float22bfloat162_rn(r);
    }
    *(uint4*)(g_G + base) = outv;
}

// ---------------------------------------------------------------------------
// k_gemm: 128x128 upper-triangle tile (bi<=bj), bf16 mma.sync + ldmatrix.
// K-chunk 64, double-buffered dynamic smem (72 KB), 1 sync per chunk.
//   pass 1: D = G*G^T       -> H = G + D (bf16)
//   pass 2: D = G*H^T (=S)  -> cov epilogue into out (strictly upper)
// ---------------------------------------------------------------------------
static constexpr int KC  = 64;     // k-chunk
static constexpr int LDT = 72;     // smem row stride (bf16 elems) = 144B, conflict-free
static constexpr int BUF = 128 * LDT * 2;          // 18432 bytes per operand buffer
static constexpr int SMEM_DYN = 4 * BUF;           // 73728

__global__ void __launch_bounds__(256, 2) k_gemm(int pass, float* out, long long covBase) {
    extern __shared__ __align__(16) char dsm[];

    int rem = blockIdx.x;
    int bi = 0;
    while (rem >= NB - bi) { rem -= NB - bi; bi++; }
    int bj = bi + rem;
    int i0 = bi * 128, j0 = bj * 128;

    const __nv_bfloat16* Aop = g_G;
    const __nv_bfloat16* Bop = (pass == 1) ? g_G : g_H;

    int tid = threadIdx.x, lane = tid & 31, wid = tid >> 5;
    int wr = wid >> 2, wc = wid & 3;
    int gID = lane >> 2, tig = lane & 3;

    uint32_t sAu = smem_u32(dsm);              // [sA0 sA1 sB0 sB1]
    uint32_t sBu = sAu + 2 * BUF;

    // A fragment ldmatrix offsets (x4): rows (lane&15), k-half (lane>>4)
    int la16 = lane & 15, lkh = lane >> 4;
    uint32_t aoff[4];
#pragma unroll
    for (int mi = 0; mi < 4; mi++)
        aoff[mi] = (uint32_t)(((wr * 64 + mi * 16 + la16) * LDT + lkh * 8) * 2);
    // B fragment ldmatrix offsets (x4 covering ni-pair): see lane-group mapping
    uint32_t boff4[2];
#pragma unroll
    for (int p = 0; p < 2; p++) {
        int nrow = wc * 32 + (2 * p + (lane >> 4)) * 8 + (lane & 7);
        int kh = (lane >> 3) & 1;
        boff4[p] = (uint32_t)((nrow * LDT + kh * 8) * 2);
    }

    float acc[4][4][4];
#pragma unroll
    for (int a = 0; a < 4; a++)
#pragma unroll
        for (int b = 0; b < 4; b++)
#pragma unroll
            for (int c = 0; c < 4; c++) acc[a][b][c] = 0.f;

    // copy slots: 1024 16B-slots per operand per chunk; 4 per thread
    int r_[4], g_[4];
    uint32_t soff[4];
#pragma unroll
    for (int t = 0; t < 4; t++) {
        int q = tid + t * 256;
        r_[t] = q >> 3; g_[t] = q & 7;
        soff[t] = (uint32_t)(r_[t] * LDT + g_[t] * 8) * 2;
    }

#pragma unroll
    for (int t = 0; t < 4; t++) {
        cp16(sAu + soff[t], Aop + (size_t)(i0 + r_[t]) * N + g_[t] * 8);
        cp16(sBu + soff[t], Bop + (size_t)(j0 + r_[t]) * N + g_[t] * 8);
    }
    CP_COMMIT();
    CP_WAITN(0);
    __syncthreads();

    const int NCH = N / KC;   // 64
    for (int c = 0; c < NCH; c++) {
        uint32_t bufo = (uint32_t)(c & 1) * BUF;
        if (c + 1 < NCH) {
            int kc = (c + 1) * KC;
            uint32_t bo = (uint32_t)((c + 1) & 1) * BUF;
#pragma unroll
            for (int t = 0; t < 4; t++) {
                cp16(sAu + bo + soff[t], Aop + (size_t)(i0 + r_[t]) * N + kc + g_[t] * 8);
                cp16(sBu + bo + soff[t], Bop + (size_t)(j0 + r_[t]) * N + kc + g_[t] * 8);
            }
            CP_COMMIT();
        }
#pragma unroll
        for (int kk = 0; kk < KC; kk += 16) {
            uint32_t af[4][4], bfr[2][4];
#pragma unroll
            for (int mi = 0; mi < 4; mi++)
                ldmatrix_x4(af[mi], sAu + bufo + aoff[mi] + kk * 2);
#pragma unroll
            for (int p = 0; p < 2; p++)
                ldmatrix_x4(bfr[p], sBu + bufo + boff4[p] + kk * 2);
#pragma unroll
            for (int mi = 0; mi < 4; mi++)
#pragma unroll
                for (int ni = 0; ni < 4; ni++)
                    mma_bf16(acc[mi][ni], af[mi], &bfr[ni >> 1][(ni & 1) * 2]);
        }
        if (c + 1 < NCH) CP_WAITN(0);
        __syncthreads();
    }

    // epilogue
#pragma unroll
    for (int mi = 0; mi < 4; mi++) {
#pragma unroll
        for (int r8 = 0; r8 < 2; r8++) {
            int row = i0 + wr * 64 + mi * 16 + gID + r8 * 8;
            if (pass == 1) {
                __nv_bfloat16* dst = g_H + (size_t)row * N;
                const __nv_bfloat16* gsrc = g_G + (size_t)row * N;
#pragma unroll
                for (int ni = 0; ni < 4; ni++) {
                    int col = j0 + wc * 32 + ni * 8 + tig * 2;
                    float2 v;
                    v.x = acc[mi][ni][r8 * 2 + 0] + __bfloat162float(gsrc[col]);
                    v.y = acc[mi][ni][r8 * 2 + 1] + __bfloat162float(gsrc[col + 1]);
                    *(__nv_bfloat162*)(dst + col) = __float22bfloat162_rn(v);
                }
            } else {
                const float* jsrc = g_Js + (size_t)row * N;
                float mrow = g_m[0][row];
                float inv_wr = 1.0f / g_w[row];
#pragma unroll
                for (int ni = 0; ni < 4; ni++) {
                    int col = j0 + wc * 32 + ni * 8 + tig * 2;
#pragma unroll
                    for (int e = 0; e < 2; e++) {
                        int gj = col + e;
                        if (gj > row) {
                            float S = acc[mi][ni][r8 * 2 + e];
                            float cov = mrow * g_m[0][gj]
                                      + CINV * (CINV * jsrc[gj] * g_d[gj] + S * g_w[gj] * inv_wr);
                            out[covBase + (size_t)row * N + gj] = cov;
                        }
                    }
                }
            }
        }
    }
}

// ---------------------------------------------------------------------------
// k_mirrorH: H[r][c] = H[c][r] for r > c
// ---------------------------------------------------------------------------
__global__ void k_mirrorH() {
    int bx = blockIdx.x, by = blockIdx.y;
    if (by < bx) return;
    __shared__ __nv_bfloat16 t[32][33];
    int tx = threadIdx.x, ty = threadIdx.y;
    t[ty][tx] = g_H[(size_t)(bx * 32 + ty) * N + (by * 32 + tx)];
    __syncthreads();
    int dr = by * 32 + ty, dc = bx * 32 + tx;
    if (dr > dc) g_H[(size_t)dr * N + dc] = t[tx][ty];
}

// ---------------------------------------------------------------------------
// kernel_launch
// ---------------------------------------------------------------------------
extern "C" void kernel_launch(void* const* d_in, const int* in_sizes, int n_in,
                              void* d_out, int out_size) {
    const float* h = nullptr;
    const float* J = nullptr;
    for (int i = 0; i < n_in; i++) {
        if (in_sizes[i] == N * N)   J = (const float*)d_in[i];
        else if (in_sizes[i] == N)  h = (const float*)d_in[i];
    }
    float* out = (float*)d_out;
    long long covBase = ((long long)out_size >= (long long)N * N + N) ? N : 0;

    cudaFuncSetAttribute(k_gemm, cudaFuncAttributeMaxDynamicSharedMemorySize, SMEM_DYN);

    k_zero<<<4096, 256>>>(out, (long long)out_size);
    k_prep<<<NT * (NT + 1) / 2, dim3(32, 32)>>>(J);
    k_minit<<<16, 256>>>(h);
    for (int t = 0; t < TOT_ITERS; t++) {
        if (t < SPLIT) k_iter_bf16<<<N / 4, 256>>>(h, t & 1);
        else           k_iter_f32 <<<N / 2, 256>>>(h, t & 1);
    }
    k_vec<<<16, 256>>>(out, covBase > 0 ? 1 : 0);
    k_buildG<<<(int)(((size_t)N * N / 8 + 255) / 256), 256>>>();
    k_gemm<<<NB * (NB + 1) / 2, 256, SMEM_DYN>>>(1, out, covBase);
    k_mirrorH<<<dim3(N / 32, N / 32), dim3(32, 32)>>>();
    k_gemm<<<NB * (NB + 1) / 2, 256, SMEM_DYN>>>(2, out, covBase);
}

// round 12
// speedup vs baseline: 2.4828x; 1.0317x over previous
#include <cuda_runtime.h>
#include <cuda_bf16.h>
#include <cstdint>
#include <cstddef>

static constexpr int   N     = 4096;
static constexpr int   NB    = 32;            // 128-tiles per side
static constexpr int   NT    = 128;           // 32-tiles per side
static constexpr int   TOT_ITERS = 14;        // 12 bf16 + 2 fp32 polish (even -> m ends in g_m[0])
static constexpr int   SPLIT = 12;
static constexpr float CINV  = 1.0f / 1.000001f;

// ---------------------------------------------------------------------------
// Device scratch (allocation-free rule: __device__ globals)
// ---------------------------------------------------------------------------
static __device__ float         g_Js[(size_t)N * N];  // 64 MB symmetrized J (fp32)
static __device__ __nv_bfloat16 g_G [(size_t)N * N];  // 32 MB: Js(bf16) during iters, then G
static __device__ __nv_bfloat16 g_H [(size_t)N * N];  // 32 MB: H = G + G^2
static __device__ float         g_m [2][N];
static __device__ float         g_d [N];
static __device__ float         g_w [N];

// ---------------------------------------------------------------------------
// PTX wrappers (all baseline PTX: sm_75/sm_80 features, compute_103-safe)
// ---------------------------------------------------------------------------
__device__ __forceinline__ void mma_bf16(float* c, const uint32_t* a, const uint32_t* b) {
    asm volatile(
        "mma.sync.aligned.m16n8k16.row.col.f32.bf16.bf16.f32 "
        "{%0,%1,%2,%3}, {%4,%5,%6,%7}, {%8,%9}, {%0,%1,%2,%3};\n"
        : "+f"(c[0]), "+f"(c[1]), "+f"(c[2]), "+f"(c[3])
        : "r"(a[0]), "r"(a[1]), "r"(a[2]), "r"(a[3]), "r"(b[0]), "r"(b[1]));
}
__device__ __forceinline__ void ldmatrix_x4(uint32_t* r, uint32_t addr) {
    asm volatile("ldmatrix.sync.aligned.m8n8.x4.shared.b16 {%0,%1,%2,%3}, [%4];"
                 : "=r"(r[0]), "=r"(r[1]), "=r"(r[2]), "=r"(r[3]) : "r"(addr));
}
__device__ __forceinline__ uint32_t smem_u32(const void* p) {
    uint32_t a;
    asm("{ .reg .u64 t; cvta.to.shared.u64 t, %1; cvt.u32.u64 %0, t; }" : "=r"(a) : "l"(p));
    return a;
}
__device__ __forceinline__ void cp16(uint32_t dst, const void* src) {
    asm volatile("cp.async.cg.shared.global [%0], [%1], 16;" :: "r"(dst), "l"(src));
}
#define CP_COMMIT()  asm volatile("cp.async.commit_group;" ::: "memory")
#define CP_WAITN(n)  asm volatile("cp.async.wait_group %0;" :: "n"(n) : "memory")

// ---------------------------------------------------------------------------
// k_zero_tri: zero cov lower triangle + diagonal (the only part pass-2 never
// writes). Block per row; float4 fast path.
// ---------------------------------------------------------------------------
__global__ void k_zero_tri(float* out, long long covBase) {
    int r = blockIdx.x;
    float* row = out + covBase + (size_t)r * N;
    int nz = r + 1;                  // zero cols [0..r]
    int nq = nz >> 2;                // full float4s
    float4* row4 = (float4*)row;
    for (int q = threadIdx.x; q < nq; q += blockDim.x)
        row4[q] = make_float4(0.f, 0.f, 0.f, 0.f);
    int tail = nq << 2;
    if (threadIdx.x < nz - tail) row[tail + threadIdx.x] = 0.f;
}

// ---------------------------------------------------------------------------
// k_prep: Js = sym(J) with zero diag (fp32) + bf16 copy; tile-pair version
// ---------------------------------------------------------------------------
__global__ void k_prep(const float* __restrict__ J) {
    int rem = blockIdx.x;
    int bi = 0;
    while (rem >= NT - bi) { rem -= NT - bi; bi++; }
    int bj = bi + rem;
    __shared__ float ta[32][33];
    __shared__ float tb[32][33];
    int r = threadIdx.y, c = threadIdx.x;
    ta[r][c] = J[(size_t)(bi * 32 + r) * N + (bj * 32 + c)];
    tb[r][c] = J[(size_t)(bj * 32 + r) * N + (bi * 32 + c)];
    __syncthreads();
    {
        int gi = bi * 32 + r, gj = bj * 32 + c;
        float v = (gi == gj) ? 0.0f : 0.5f * (ta[r][c] + tb[c][r]);
        size_t idx = (size_t)gi * N + gj;
        g_Js[idx] = v;
        g_G[idx]  = __float2bfloat16(v);
    }
    if (bi != bj) {
        int gi = bj * 32 + r, gj = bi * 32 + c;
        float v = 0.5f * (tb[r][c] + ta[c][r]);
        size_t idx = (size_t)gi * N + gj;
        g_Js[idx] = v;
        g_G[idx]  = __float2bfloat16(v);
    }
}

// ---------------------------------------------------------------------------
// m0 = tanh(h)
// ---------------------------------------------------------------------------
__global__ void k_minit(const float* __restrict__ h) {
    int i = blockIdx.x * blockDim.x + threadIdx.x;
    if (i < N) g_m[0][i] = tanhf(h[i]);
}

// ---------------------------------------------------------------------------
// bf16 iteration: 4 rows/CTA, 4-stage cp.async pipeline, BARRIER-FREE stages
// ---------------------------------------------------------------------------
__global__ void __launch_bounds__(256) k_iter_bf16(const float* __restrict__ h, int pin) {
    __shared__ __align__(16) __nv_bfloat16 sj[4][N];   // 32 KB
    int row0 = blockIdx.x * 4;
    const float* mi_v = g_m[pin];
    const float4* mv = (const float4*)mi_v;
    uint32_t sb = smem_u32(&sj[0][0]);
    int tid = threadIdx.x;
    int half = tid >> 7;          // 0 or 1
    int tcol = tid & 127;
    int r0 = half * 2;

#pragma unroll
    for (int s = 0; s < 4; s++) {
#pragma unroll
        for (int p = 0; p < 2; p++) {
            int r = r0 + p;
            int cc = 128 * s + tcol;                       // 16B chunk (8 bf16)
            cp16(sb + ((uint32_t)r * N + (uint32_t)cc * 8) * 2,
                 g_G + (size_t)(row0 + r) * N + (size_t)cc * 8);
        }
        CP_COMMIT();
    }

    float s1[2] = {0.f, 0.f}, s2[2] = {0.f, 0.f};
#pragma unroll
    for (int s = 0; s < 4; s++) {
        if      (s == 0) CP_WAITN(3);
        else if (s == 1) CP_WAITN(2);
        else if (s == 2) CP_WAITN(1);
        else             CP_WAITN(0);
        int cc = 128 * s + tcol;
        float4 ma = mv[2 * cc], mb = mv[2 * cc + 1];
        float pa[8] = {ma.x, ma.y, ma.z, ma.w, mb.x, mb.y, mb.z, mb.w};
        float pb[8];
#pragma unroll
        for (int e = 0; e < 8; e++) pb[e] = pa[e] * (1.f - pa[e]);
#pragma unroll
        for (int p = 0; p < 2; p++) {
            uint4 v = *(const uint4*)&sj[r0 + p][cc * 8];
            const __nv_bfloat162* b2 = reinterpret_cast<const __nv_bfloat162*>(&v);
            float2 a0 = __bfloat1622float2(b2[0]);
            float2 a1 = __bfloat1622float2(b2[1]);
            float2 a2 = __bfloat1622float2(b2[2]);
            float2 a3 = __bfloat1622float2(b2[3]);
            float av[8] = {a0.x, a0.y, a1.x, a1.y, a2.x, a2.y, a3.x, a3.y};
#pragma unroll
            for (int e = 0; e < 8; e++) {
                s1[p] = fmaf(av[e], pa[e], s1[p]);
                s2[p] = fmaf(av[e] * av[e], pb[e], s2[p]);
            }
        }
    }

    __shared__ float rs1[8][2], rs2[8][2];
    int lane = tid & 31, w = tid >> 5;
#pragma unroll
    for (int p = 0; p < 2; p++) {
#pragma unroll
        for (int o = 16; o; o >>= 1) {
            s1[p] += __shfl_xor_sync(0xFFFFFFFFu, s1[p], o);
            s2[p] += __shfl_xor_sync(0xFFFFFFFFu, s2[p], o);
        }
        if (lane == 0) { rs1[w][p] = s1[p]; rs2[w][p] = s2[p]; }
    }
    __syncthreads();
    if (tid < 4) {
        int r = tid;
        int wbase = (r >> 1) * 4;
        int idx = r & 1;
        float a = 0.f, b = 0.f;
#pragma unroll
        for (int ww = 0; ww < 4; ww++) { a += rs1[wbase + ww][idx]; b += rs2[wbase + ww][idx]; }
        int row = row0 + r;
        float mi = mi_v[row];
        g_m[pin ^ 1][row] = 0.5f * (mi + tanhf(h[row] + a - mi * b));
    }
}

// ---------------------------------------------------------------------------
// fp32 polish: 2 rows/CTA, barrier-free 4-stage pipeline
// ---------------------------------------------------------------------------
__global__ void __launch_bounds__(256) k_iter_f32(const float* __restrict__ h, int pin) {
    __shared__ __align__(16) float sj[2][N];            // 32 KB
    int row0 = blockIdx.x * 2;
    const float* mi_v = g_m[pin];
    const float4* mv = (const float4*)mi_v;
    uint32_t sb = smem_u32(&sj[0][0]);
    int tid = threadIdx.x;
    int half = tid >> 7;
    int tcol = tid & 127;

#pragma unroll
    for (int s = 0; s < 4; s++) {
#pragma unroll
        for (int p = 0; p < 2; p++) {
            int cc = 256 * s + tcol + 128 * p;
            cp16(sb + ((uint32_t)half * N + (uint32_t)cc * 4) * 4,
                 g_Js + (size_t)(row0 + half) * N + (size_t)cc * 4);
        }
        CP_COMMIT();
    }

    float s1 = 0.f, s2 = 0.f;
#pragma unroll
    for (int s = 0; s < 4; s++) {
        if      (s == 0) CP_WAITN(3);
        else if (s == 1) CP_WAITN(2);
        else if (s == 2) CP_WAITN(1);
        else             CP_WAITN(0);
#pragma unroll
        for (int p = 0; p < 2; p++) {
            int cc = 256 * s + tcol + 128 * p;
            float4 a = *(const float4*)&sj[half][cc * 4];
            float4 mq = mv[cc];
            float pa[4] = {mq.x, mq.y, mq.z, mq.w};
            float av[4] = {a.x, a.y, a.z, a.w};
#pragma unroll
            for (int e = 0; e < 4; e++) {
                float pb = pa[e] * (1.f - pa[e]);
                s1 = fmaf(av[e], pa[e], s1);
                s2 = fmaf(av[e] * av[e], pb, s2);
            }
        }
    }

    __shared__ float rs1[8], rs2[8];
    int lane = tid & 31, w = tid >> 5;
#pragma unroll
    for (int o = 16; o; o >>= 1) {
        s1 += __shfl_xor_sync(0xFFFFFFFFu, s1, o);
        s2 += __shfl_xor_sync(0xFFFFFFFFu, s2, o);
    }
    if (lane == 0) { rs1[w] = s1; rs2[w] = s2; }
    __syncthreads();
    if (tid < 2) {
        int r = tid;
        float a = 0.f, b = 0.f;
#pragma unroll
        for (int ww = 0; ww < 4; ww++) { a += rs1[r * 4 + ww]; b += rs2[r * 4 + ww]; }
        int row = row0 + r;
        float mi = mi_v[row];
        g_m[pin ^ 1][row] = 0.5f * (mi + tanhf(h[row] + a - mi * b));
    }
}

// ---------------------------------------------------------------------------
// k_vec: finalize m, compute d, w, write m to out
// ---------------------------------------------------------------------------
__global__ void k_vec(float* out, int writeM) {
    int i = blockIdx.x * blockDim.x + threadIdx.x;
    if (i < N) {
        float m = g_m[0][i];
        float d = 1.0f - m * m;
        g_d[i] = d;
        g_w[i] = sqrtf(d);
        if (writeM) out[i] = m;
    }
}

// ---------------------------------------------------------------------------
// k_buildG: G_ij = CINV * w_i * G_ij * w_j (in-place over bf16(Js))
// ---------------------------------------------------------------------------
__global__ void k_buildG() {
    size_t q = (size_t)blockIdx.x * blockDim.x + threadIdx.x;  // 8-elem group
    size_t nq = (size_t)N * N / 8;
    if (q >= nq) return;
    size_t base = q * 8;
    int i = (int)(base >> 12);
    int j = (int)(base & (N - 1));
    uint4 v = *(const uint4*)(g_G + base);
    const __nv_bfloat162* b2 = reinterpret_cast<const __nv_bfloat162*>(&v);
    float s = CINV * g_w[i];
    uint4 outv;
    __nv_bfloat162* o2 = reinterpret_cast<__nv_bfloat162*>(&outv);
#pragma unroll
    for (int e = 0; e < 4; e++) {
        float2 a = __bfloat1622float2(b2[e]);
        float2 r;
        r.x = s * g_w[j + 2 * e]     * a.x;
        r.y = s * g_w[j + 2 * e + 1] * a.y;
        o2[e] = __float22bfloat162_rn(r);
    }
    *(uint4*)(g_G + base) = outv;
}

// ---------------------------------------------------------------------------
// k_gemm: 128x128 upper-triangle tile (bi<=bj), bf16 mma.sync + ldmatrix.
// K-chunk 64, double-buffered dynamic smem (72 KB), 1 sync per chunk.
//   pass 1: D = G*G^T       -> H = G + D (bf16)
//   pass 2: D = G*H^T (=S)  -> cov epilogue into out (strictly upper)
// ---------------------------------------------------------------------------
static constexpr int KC  = 64;     // k-chunk
static constexpr int LDT = 72;     // smem row stride (bf16 elems) = 144B, conflict-free
static constexpr int BUF = 128 * LDT * 2;          // 18432 bytes per operand buffer
static constexpr int SMEM_DYN = 4 * BUF;           // 73728

__global__ void __launch_bounds__(256, 2) k_gemm(int pass, float* out, long long covBase) {
    extern __shared__ __align__(16) char dsm[];

    int rem = blockIdx.x;
    int bi = 0;
    while (rem >= NB - bi) { rem -= NB - bi; bi++; }
    int bj = bi + rem;
    int i0 = bi * 128, j0 = bj * 128;

    const __nv_bfloat16* Aop = g_G;
    const __nv_bfloat16* Bop = (pass == 1) ? g_G : g_H;

    int tid = threadIdx.x, lane = tid & 31, wid = tid >> 5;
    int wr = wid >> 2, wc = wid & 3;
    int gID = lane >> 2, tig = lane & 3;

    uint32_t sAu = smem_u32(dsm);              // [sA0 sA1 sB0 sB1]
    uint32_t sBu = sAu + 2 * BUF;

    int la16 = lane & 15, lkh = lane >> 4;
    uint32_t aoff[4];
#pragma unroll
    for (int mi = 0; mi < 4; mi++)
        aoff[mi] = (uint32_t)(((wr * 64 + mi * 16 + la16) * LDT + lkh * 8) * 2);
    uint32_t boff4[2];
#pragma unroll
    for (int p = 0; p < 2; p++) {
        int nrow = wc * 32 + (2 * p + (lane >> 4)) * 8 + (lane & 7);
        int kh = (lane >> 3) & 1;
        boff4[p] = (uint32_t)((nrow * LDT + kh * 8) * 2);
    }

    float acc[4][4][4];
#pragma unroll
    for (int a = 0; a < 4; a++)
#pragma unroll
        for (int b = 0; b < 4; b++)
#pragma unroll
            for (int c = 0; c < 4; c++) acc[a][b][c] = 0.f;

    int r_[4], g_[4];
    uint32_t soff[4];
#pragma unroll
    for (int t = 0; t < 4; t++) {
        int q = tid + t * 256;
        r_[t] = q >> 3; g_[t] = q & 7;
        soff[t] = (uint32_t)(r_[t] * LDT + g_[t] * 8) * 2;
    }

#pragma unroll
    for (int t = 0; t < 4; t++) {
        cp16(sAu + soff[t], Aop + (size_t)(i0 + r_[t]) * N + g_[t] * 8);
        cp16(sBu + soff[t], Bop + (size_t)(j0 + r_[t]) * N + g_[t] * 8);
    }
    CP_COMMIT();
    CP_WAITN(0);
    __syncthreads();

    const int NCH = N / KC;   // 64
    for (int c = 0; c < NCH; c++) {
        uint32_t bufo = (uint32_t)(c & 1) * BUF;
        if (c + 1 < NCH) {
            int kc = (c + 1) * KC;
            uint32_t bo = (uint32_t)((c + 1) & 1) * BUF;
#pragma unroll
            for (int t = 0; t < 4; t++) {
                cp16(sAu + bo + soff[t], Aop + (size_t)(i0 + r_[t]) * N + kc + g_[t] * 8);
                cp16(sBu + bo + soff[t], Bop + (size_t)(j0 + r_[t]) * N + kc + g_[t] * 8);
            }
            CP_COMMIT();
        }
#pragma unroll
        for (int kk = 0; kk < KC; kk += 16) {
            uint32_t af[4][4], bfr[2][4];
#pragma unroll
            for (int mi = 0; mi < 4; mi++)
                ldmatrix_x4(af[mi], sAu + bufo + aoff[mi] + kk * 2);
#pragma unroll
            for (int p = 0; p < 2; p++)
                ldmatrix_x4(bfr[p], sBu + bufo + boff4[p] + kk * 2);
#pragma unroll
            for (int mi = 0; mi < 4; mi++)
#pragma unroll
                for (int ni = 0; ni < 4; ni++)
                    mma_bf16(acc[mi][ni], af[mi], &bfr[ni >> 1][(ni & 1) * 2]);
        }
        if (c + 1 < NCH) CP_WAITN(0);
        __syncthreads();
    }

    // epilogue
#pragma unroll
    for (int mi = 0; mi < 4; mi++) {
#pragma unroll
        for (int r8 = 0; r8 < 2; r8++) {
            int row = i0 + wr * 64 + mi * 16 + gID + r8 * 8;
            if (pass == 1) {
                __nv_bfloat16* dst = g_H + (size_t)row * N;
                const __nv_bfloat16* gsrc = g_G + (size_t)row * N;
#pragma unroll
                for (int ni = 0; ni < 4; ni++) {
                    int col = j0 + wc * 32 + ni * 8 + tig * 2;
                    float2 v;
                    v.x = acc[mi][ni][r8 * 2 + 0] + __bfloat162float(gsrc[col]);
                    v.y = acc[mi][ni][r8 * 2 + 1] + __bfloat162float(gsrc[col + 1]);
                    *(__nv_bfloat162*)(dst + col) = __float22bfloat162_rn(v);
                }
            } else {
                const float* jsrc = g_Js + (size_t)row * N;
                float mrow = g_m[0][row];
                float inv_wr = 1.0f / g_w[row];
#pragma unroll
                for (int ni = 0; ni < 4; ni++) {
                    int col = j0 + wc * 32 + ni * 8 + tig * 2;
#pragma unroll
                    for (int e = 0; e < 2; e++) {
                        int gj = col + e;
                        if (gj > row) {
                            float S = acc[mi][ni][r8 * 2 + e];
                            float cov = mrow * g_m[0][gj]
                                      + CINV * (CINV * jsrc[gj] * g_d[gj] + S * g_w[gj] * inv_wr);
                            out[covBase + (size_t)row * N + gj] = cov;
                        }
                    }
                }
            }
        }
    }
}

// ---------------------------------------------------------------------------
// k_mirrorH: H[r][c] = H[c][r] for r > c
// ---------------------------------------------------------------------------
__global__ void k_mirrorH() {
    int bx = blockIdx.x, by = blockIdx.y;
    if (by < bx) return;
    __shared__ __nv_bfloat16 t[32][33];
    int tx = threadIdx.x, ty = threadIdx.y;
    t[ty][tx] = g_H[(size_t)(bx * 32 + ty) * N + (by * 32 + tx)];
    __syncthreads();
    int dr = by * 32 + ty, dc = bx * 32 + tx;
    if (dr > dc) g_H[(size_t)dr * N + dc] = t[tx][ty];
}

// ---------------------------------------------------------------------------
// kernel_launch
// ---------------------------------------------------------------------------
extern "C" void kernel_launch(void* const* d_in, const int* in_sizes, int n_in,
                              void* d_out, int out_size) {
    const float* h = nullptr;
    const float* J = nullptr;
    for (int i = 0; i < n_in; i++) {
        if (in_sizes[i] == N * N)   J = (const float*)d_in[i];
        else if (in_sizes[i] == N)  h = (const float*)d_in[i];
    }
    float* out = (float*)d_out;
    long long covBase = ((long long)out_size >= (long long)N * N + N) ? N : 0;

    cudaFuncSetAttribute(k_gemm, cudaFuncAttributeMaxDynamicSharedMemorySize, SMEM_DYN);

    k_zero_tri<<<N, 256>>>(out, covBase);
    k_prep<<<NT * (NT + 1) / 2, dim3(32, 32)>>>(J);
    k_minit<<<16, 256>>>(h);
    for (int t = 0; t < TOT_ITERS; t++) {
        if (t < SPLIT) k_iter_bf16<<<N / 4, 256>>>(h, t & 1);
        else           k_iter_f32 <<<N / 2, 256>>>(h, t & 1);
    }
    k_vec<<<16, 256>>>(out, covBase > 0 ? 1 : 0);
    k_buildG<<<(int)(((size_t)N * N / 8 + 255) / 256), 256>>>();
    k_gemm<<<NB * (NB + 1) / 2, 256, SMEM_DYN>>>(1, out, covBase);
    k_mirrorH<<<dim3(N / 32, N / 32), dim3(32, 32)>>>();
    k_gemm<<<NB * (NB + 1) / 2, 256, SMEM_DYN>>>(2, out, covBase);
}